// round 2
// baseline (speedup 1.0000x reference)
#include <cuda_runtime.h>
#include <math.h>

#define NB    512          // num_windows * batch
#define NT    98           // tokens per window
#define DIMC  512
#define NH    16
#define HD    32
#define NWIN  64
#define MROWS (NB*NT)      // 50176
#define QK_SCALE 0.17677669529663687f   // 32^-0.5

// ---------------- scratch (device globals; no runtime alloc allowed) -------
__device__ float g_q[(size_t)NB*NH*NT*HD];
__device__ float g_k[(size_t)NB*NH*NT*HD];
__device__ float g_v[(size_t)NB*NH*NT*HD];
__device__ float g_o[(size_t)MROWS*DIMC];
__device__ float g_bias[NH*NT*NT];

// ---------------- relative position bias gather ----------------------------
__global__ void bias_gather_kernel(const float* __restrict__ bt,
                                   const int*   __restrict__ ri)
{
    int idx = blockIdx.x * blockDim.x + threadIdx.x;
    if (idx < NH*NT*NT) {
        int h  = idx / (NT*NT);
        int ij = idx - h*(NT*NT);
        g_bias[idx] = bt[ri[ij]*NH + h];
    }
}

// ---------------- SGEMM: C[M,N] = A[M,K] @ B[N,K]^T + bias[N] --------------
// MODE 0: A = g_o (proj input), plain write to C (ldc = N)
// MODE 1: A = x, epilogue scatters into g_q/g_k/g_v (q scaled)
// K is hardcoded 512. M,N multiples of 128.
template<int MODE>
__global__ __launch_bounds__(256)
void sgemm_tn(const float* __restrict__ A, const float* __restrict__ B,
              const float* __restrict__ bias, float* __restrict__ C, int ldc)
{
    __shared__ float As[16][132];   // pad 132 (=33*4 words) keeps 16B align
    __shared__ float Bs[16][132];

    const int tid = threadIdx.x;
    const int m0 = blockIdx.y * 128;
    const int n0 = blockIdx.x * 128;
    const int tr = tid >> 4;          // 0..15
    const int tc = tid & 15;          // 0..15
    const int lRow = tid >> 2;        // 0..63
    const int lCol = (tid & 3) << 2;  // 0,4,8,12

    const float* Aptr = (MODE == 0) ? g_o : A;

    float acc[8][8];
    #pragma unroll
    for (int i = 0; i < 8; i++)
        #pragma unroll
        for (int j = 0; j < 8; j++) acc[i][j] = 0.f;

    for (int k0 = 0; k0 < DIMC; k0 += 16) {
        #pragma unroll
        for (int r = 0; r < 2; r++) {
            float4 ta = *(const float4*)(Aptr + (size_t)(m0 + lRow + 64*r)*DIMC + k0 + lCol);
            As[lCol+0][lRow+64*r] = ta.x;
            As[lCol+1][lRow+64*r] = ta.y;
            As[lCol+2][lRow+64*r] = ta.z;
            As[lCol+3][lRow+64*r] = ta.w;
            float4 tb = *(const float4*)(B + (size_t)(n0 + lRow + 64*r)*DIMC + k0 + lCol);
            Bs[lCol+0][lRow+64*r] = tb.x;
            Bs[lCol+1][lRow+64*r] = tb.y;
            Bs[lCol+2][lRow+64*r] = tb.z;
            Bs[lCol+3][lRow+64*r] = tb.w;
        }
        __syncthreads();
        #pragma unroll
        for (int kk = 0; kk < 16; kk++) {
            float4 a0 = *(const float4*)&As[kk][tr*4];
            float4 a1 = *(const float4*)&As[kk][tr*4 + 64];
            float4 b0 = *(const float4*)&Bs[kk][tc*4];
            float4 b1 = *(const float4*)&Bs[kk][tc*4 + 64];
            float av[8] = {a0.x,a0.y,a0.z,a0.w,a1.x,a1.y,a1.z,a1.w};
            float bv[8] = {b0.x,b0.y,b0.z,b0.w,b1.x,b1.y,b1.z,b1.w};
            #pragma unroll
            for (int i = 0; i < 8; i++)
                #pragma unroll
                for (int j = 0; j < 8; j++)
                    acc[i][j] += av[i]*bv[j];
        }
        __syncthreads();
    }

    #pragma unroll
    for (int i = 0; i < 8; i++) {
        int row = m0 + ((i < 4) ? tr*4 + i : 64 + tr*4 + (i-4));
        #pragma unroll
        for (int j = 0; j < 8; j++) {
            int col = n0 + ((j < 4) ? tc*4 + j : 64 + tc*4 + (j-4));
            float val = acc[i][j] + bias[col];
            if (MODE == 0) {
                C[(size_t)row*ldc + col] = val;
            } else {
                int which = col >> 9;         // 0=q 1=k 2=v
                int rem   = col & 511;
                int head  = rem >> 5;
                int d     = rem & 31;
                int b     = row / NT;
                int n     = row - b*NT;
                size_t idx = ((size_t)((b*NH + head)*NT + n))*HD + d;
                if (which == 0)      g_q[idx] = val * QK_SCALE;
                else if (which == 1) g_k[idx] = val;
                else                 g_v[idx] = val;
            }
        }
    }
}

// ---------------- attention: one block per (b,h) ---------------------------
#define SM_K    (NT*33)
#define SM_V    (2*NT*33)
#define SM_S    (3*NT*33)
#define SM_RINV (3*NT*33 + NT*NT)
#define SM_FLOATS (3*NT*33 + NT*NT + NT)

__global__ __launch_bounds__(256)
void attn_kernel(const float* __restrict__ mask)
{
    extern __shared__ float sm[];
    float* qs   = sm;
    float* ks   = sm + SM_K;
    float* vs   = sm + SM_V;
    float* sc   = sm + SM_S;
    float* rinv = sm + SM_RINV;

    const int bh = blockIdx.x;
    const int b  = bh >> 4;
    const int h  = bh & 15;
    const int w  = b & (NWIN - 1);
    const float* mk = mask   + (size_t)w * NT * NT;
    const float* bi = g_bias + (size_t)h * NT * NT;
    const size_t base = (size_t)bh * NT * HD;

    const int tid = threadIdx.x;
    for (int idx = tid; idx < NT*HD; idx += 256) {
        int r = idx >> 5, c = idx & 31;
        qs[r*33 + c] = g_q[base + idx];
        ks[r*33 + c] = g_k[base + idx];
        vs[r*33 + c] = g_v[base + idx];
    }
    __syncthreads();

    const int warp = tid >> 5, lane = tid & 31;

    // scores = (q*scale) @ k^T + bias + mask
    for (int i = warp; i < NT; i += 8) {
        float rq[32];
        #pragma unroll
        for (int kk = 0; kk < 32; kk++) rq[kk] = qs[i*33 + kk];
        for (int j = lane; j < NT; j += 32) {
            float acc = 0.f;
            #pragma unroll
            for (int kk = 0; kk < 32; kk++) acc += rq[kk] * ks[j*33 + kk];
            sc[i*NT + j] = acc + bi[i*NT + j] + mk[i*NT + j];
        }
    }
    __syncthreads();

    // row softmax (store exp; 1/sum deferred to PV epilogue)
    for (int i = warp; i < NT; i += 8) {
        float mx = -1e30f;
        for (int j = lane; j < NT; j += 32) mx = fmaxf(mx, sc[i*NT + j]);
        #pragma unroll
        for (int off = 16; off; off >>= 1)
            mx = fmaxf(mx, __shfl_xor_sync(0xffffffffu, mx, off));
        float s = 0.f;
        for (int j = lane; j < NT; j += 32) {
            float e = __expf(sc[i*NT + j] - mx);
            sc[i*NT + j] = e;
            s += e;
        }
        #pragma unroll
        for (int off = 16; off; off >>= 1)
            s += __shfl_xor_sync(0xffffffffu, s, off);
        if (lane == 0) rinv[i] = 1.f / s;
    }
    __syncthreads();

    // out = P @ V, written as [b, n, h*32+d] (proj input layout)
    const int bq = b * NT;
    for (int i = warp; i < NT; i += 8) {
        float acc = 0.f;
        const float* sr = sc + i*NT;
        #pragma unroll 2
        for (int j = 0; j < NT; j++) acc += sr[j] * vs[j*33 + lane];
        g_o[((size_t)(bq + i))*DIMC + h*HD + lane] = acc * rinv[i];
    }
}

// ---------------- launch ----------------------------------------------------
extern "C" void kernel_launch(void* const* d_in, const int* in_sizes, int n_in,
                              void* d_out, int out_size)
{
    const float* x          = (const float*)d_in[0];
    const float* mask       = (const float*)d_in[1];
    const float* qkv_w      = (const float*)d_in[2];
    const float* qkv_b      = (const float*)d_in[3];
    const float* proj_w     = (const float*)d_in[4];
    const float* proj_b     = (const float*)d_in[5];
    const float* bias_table = (const float*)d_in[6];
    const int*   rel_index  = (const int*)  d_in[7];
    float* out = (float*)d_out;

    const int smem = SM_FLOATS * (int)sizeof(float);   // ~77.6 KB
    cudaFuncSetAttribute(attn_kernel,
                         cudaFuncAttributeMaxDynamicSharedMemorySize, smem);

    bias_gather_kernel<<<(NH*NT*NT + 255)/256, 256>>>(bias_table, rel_index);
    sgemm_tn<1><<<dim3(1536/128, MROWS/128), 256>>>(x, qkv_w, qkv_b, nullptr, 0);
    attn_kernel<<<NB*NH, 256, smem>>>(mask);
    sgemm_tn<0><<<dim3(DIMC/128, MROWS/128), 256>>>(nullptr, proj_w, proj_b, out, DIMC);
}

// round 6
// speedup vs baseline: 1.3686x; 1.3686x over previous
#include <cuda_runtime.h>
#include <cuda_bf16.h>
#include <math.h>
#include <stdint.h>

#define NB    512
#define NT    98
#define DIMC  512
#define NH    16
#define HD    32
#define NWIN  64
#define MROWS (NB*NT)                 // 50176
#define QK_SCALE 0.17677669529663687f

// ---------------- scratch (device globals; no runtime alloc) ---------------
__device__ __align__(16) __nv_bfloat16 g_xh[(size_t)MROWS*DIMC];
__device__ __align__(16) __nv_bfloat16 g_xl[(size_t)MROWS*DIMC];
__device__ __align__(16) __nv_bfloat16 g_wh[(size_t)3*DIMC*DIMC];
__device__ __align__(16) __nv_bfloat16 g_wl[(size_t)3*DIMC*DIMC];
__device__ __align__(16) __nv_bfloat16 g_ph[(size_t)DIMC*DIMC];
__device__ __align__(16) __nv_bfloat16 g_pl[(size_t)DIMC*DIMC];
__device__ __align__(16) __nv_bfloat16 g_oh[(size_t)MROWS*DIMC];
__device__ __align__(16) __nv_bfloat16 g_ol[(size_t)MROWS*DIMC];

__device__ float g_q[(size_t)NB*NH*NT*HD];
__device__ float g_k[(size_t)NB*NH*NT*HD];
__device__ float g_v[(size_t)NB*NH*NT*HD];
__device__ float g_o[(size_t)MROWS*DIMC];
__device__ float g_bias[NH*NT*NT];

// ---------------- helpers ----------------------------------------------------
__device__ __forceinline__ uint32_t smem_u32(const void* p) {
    uint32_t a;
    asm("{ .reg .u64 t; cvta.to.shared.u64 t, %1; cvt.u32.u64 %0, t; }"
        : "=r"(a) : "l"(p));
    return a;
}
__device__ __forceinline__ void ldsm_x4(uint32_t& r0, uint32_t& r1,
                                        uint32_t& r2, uint32_t& r3, uint32_t addr) {
    asm volatile("ldmatrix.sync.aligned.m8n8.x4.shared.b16 {%0,%1,%2,%3}, [%4];"
                 : "=r"(r0), "=r"(r1), "=r"(r2), "=r"(r3) : "r"(addr));
}
__device__ __forceinline__ void mma_bf16(float* c, const uint32_t* a, const uint32_t* b) {
    asm volatile(
        "mma.sync.aligned.m16n8k16.row.col.f32.bf16.bf16.f32 "
        "{%0,%1,%2,%3}, {%4,%5,%6,%7}, {%8,%9}, {%0,%1,%2,%3};"
        : "+f"(c[0]), "+f"(c[1]), "+f"(c[2]), "+f"(c[3])
        : "r"(a[0]), "r"(a[1]), "r"(a[2]), "r"(a[3]), "r"(b[0]), "r"(b[1]));
}
// byte offset inside one 128x32-bf16 tile for (row, 16B-quarter q)
__device__ __forceinline__ uint32_t sw_off(int row, int q) {
    return (uint32_t)(row * 64 + ((q ^ ((row >> 1) & 3)) << 4));
}

// ---------------- bias gather ------------------------------------------------
__global__ void bias_gather_kernel(const float* __restrict__ bt,
                                   const int* __restrict__ ri) {
    int idx = blockIdx.x * blockDim.x + threadIdx.x;
    if (idx < NH*NT*NT) {
        int h  = idx / (NT*NT);
        int ij = idx - h*(NT*NT);
        g_bias[idx] = bt[ri[ij]*NH + h];
    }
}

// ---------------- fp32 -> bf16 hi/lo split ------------------------------------
template<int DST>
__global__ void split_kernel(const float* __restrict__ src, int n8) {
    int i = blockIdx.x * blockDim.x + threadIdx.x;
    if (i >= n8) return;
    const float* s = (DST == 3) ? g_o : src;
    __nv_bfloat16 *hi, *lo;
    if (DST == 0)      { hi = g_xh; lo = g_xl; }
    else if (DST == 1) { hi = g_wh; lo = g_wl; }
    else if (DST == 2) { hi = g_ph; lo = g_pl; }
    else               { hi = g_oh; lo = g_ol; }

    float4 a = ((const float4*)s)[2*i];
    float4 b = ((const float4*)s)[2*i + 1];
    float v[8] = {a.x, a.y, a.z, a.w, b.x, b.y, b.z, b.w};
    __nv_bfloat16 h[8], l[8];
    #pragma unroll
    for (int k = 0; k < 8; k++) {
        h[k] = __float2bfloat16(v[k]);
        l[k] = __float2bfloat16(v[k] - __bfloat162float(h[k]));
    }
    __nv_bfloat162* hi2 = (__nv_bfloat162*)hi;
    __nv_bfloat162* lo2 = (__nv_bfloat162*)lo;
    #pragma unroll
    for (int k = 0; k < 4; k++) {
        hi2[4*i + k] = __halves2bfloat162(h[2*k], h[2*k+1]);
        lo2[4*i + k] = __halves2bfloat162(l[2*k], l[2*k+1]);
    }
}

// ---------------- HMMA bf16x3 GEMM --------------------------------------------
// C[M,N] = A[M,512] @ B[N,512]^T + bias[N]
// MODE 1: A=g_xh/g_xl, B=g_wh/g_wl (N=1536), scatter q/k/v
// MODE 0: A=g_oh/g_ol, B=g_ph/g_pl (N=512), plain write
#define KCH     32
#define NCHUNK  (DIMC / KCH)        // 16
#define TILE_B  8192                // 128 rows x 64B
#define BUF_B   (4 * TILE_B)        // Ah, Al, Bh, Bl
#define SMEM_GEMM (2 * BUF_B)       // 64 KB

template<int MODE>
__global__ __launch_bounds__(256)
void gemm_mma(const float* __restrict__ bias, float* __restrict__ C) {
    extern __shared__ char smem[];
    const int tid  = threadIdx.x;
    const int lane = tid & 31;
    const int wid  = tid >> 5;
    const int wm   = wid >> 2;       // 0..1 -> m offset 64*wm
    const int wn   = wid & 3;        // 0..3 -> n offset 32*wn
    const int m0 = blockIdx.y * 128;
    const int n0 = blockIdx.x * 128;

    const __nv_bfloat16* Ah = (MODE == 1) ? g_xh : g_oh;
    const __nv_bfloat16* Al = (MODE == 1) ? g_xl : g_ol;
    const __nv_bfloat16* Bh = (MODE == 1) ? g_wh : g_ph;
    const __nv_bfloat16* Bl = (MODE == 1) ? g_wl : g_pl;

    const uint32_t sb = smem_u32(smem);

    // fill mapping: thread covers rows {r, r+64}, fixed 16B quarter q
    const int frow = tid >> 2;       // 0..63
    const int fq   = tid & 3;        // 0..3
    const uint32_t so0 = sw_off(frow,      fq);
    const uint32_t so1 = sw_off(frow + 64, fq);

    float acc[4][4][4];
    #pragma unroll
    for (int i = 0; i < 4; i++)
        #pragma unroll
        for (int j = 0; j < 4; j++)
            #pragma unroll
            for (int k = 0; k < 4; k++) acc[i][j][k] = 0.f;

    // ---- chunk 0 fill
    {
        char* bp = smem;
        #define GLD(P, RB, ROW, K0) (*(const uint4*)((P) + (size_t)((RB)+(ROW))*DIMC + (K0) + fq*8))
        uint4 p0 = GLD(Ah, m0, frow, 0), p1 = GLD(Ah, m0, frow+64, 0);
        uint4 p2 = GLD(Al, m0, frow, 0), p3 = GLD(Al, m0, frow+64, 0);
        uint4 p4 = GLD(Bh, n0, frow, 0), p5 = GLD(Bh, n0, frow+64, 0);
        uint4 p6 = GLD(Bl, n0, frow, 0), p7 = GLD(Bl, n0, frow+64, 0);
        *(uint4*)(bp + 0*TILE_B + so0) = p0; *(uint4*)(bp + 0*TILE_B + so1) = p1;
        *(uint4*)(bp + 1*TILE_B + so0) = p2; *(uint4*)(bp + 1*TILE_B + so1) = p3;
        *(uint4*)(bp + 2*TILE_B + so0) = p4; *(uint4*)(bp + 2*TILE_B + so1) = p5;
        *(uint4*)(bp + 3*TILE_B + so0) = p6; *(uint4*)(bp + 3*TILE_B + so1) = p7;
    }
    __syncthreads();

    const int lr  = lane & 15;
    const int lq2 = lane >> 4;

    for (int c = 0; c < NCHUNK; c++) {
        uint4 p0, p1, p2, p3, p4, p5, p6, p7;
        if (c + 1 < NCHUNK) {
            const int k0 = (c + 1) * KCH;
            p0 = GLD(Ah, m0, frow, k0); p1 = GLD(Ah, m0, frow+64, k0);
            p2 = GLD(Al, m0, frow, k0); p3 = GLD(Al, m0, frow+64, k0);
            p4 = GLD(Bh, n0, frow, k0); p5 = GLD(Bh, n0, frow+64, k0);
            p6 = GLD(Bl, n0, frow, k0); p7 = GLD(Bl, n0, frow+64, k0);
        }
        // ---- compute on buffer c&1
        {
            const uint32_t tba = sb + (uint32_t)(c & 1) * BUF_B;
            #pragma unroll
            for (int ks = 0; ks < 2; ks++) {
                uint32_t ah[4][4], al[4][4], bh[4][2], bl[4][2];
                #pragma unroll
                for (int mt = 0; mt < 4; mt++) {
                    int r = wm*64 + mt*16 + lr;
                    uint32_t off = sw_off(r, 2*ks + lq2);
                    ldsm_x4(ah[mt][0], ah[mt][1], ah[mt][2], ah[mt][3], tba + off);
                    ldsm_x4(al[mt][0], al[mt][1], al[mt][2], al[mt][3], tba + TILE_B + off);
                }
                #pragma unroll
                for (int g2 = 0; g2 < 2; g2++) {
                    int r = wn*32 + g2*16 + lr;
                    uint32_t off = sw_off(r, 2*ks + lq2);
                    uint32_t t0, t1, t2, t3;
                    ldsm_x4(t0, t1, t2, t3, tba + 2*TILE_B + off);
                    bh[2*g2][0] = t0; bh[2*g2][1] = t2;
                    bh[2*g2+1][0] = t1; bh[2*g2+1][1] = t3;
                    ldsm_x4(t0, t1, t2, t3, tba + 3*TILE_B + off);
                    bl[2*g2][0] = t0; bl[2*g2][1] = t2;
                    bl[2*g2+1][0] = t1; bl[2*g2+1][1] = t3;
                }
                #pragma unroll
                for (int mt = 0; mt < 4; mt++)
                    #pragma unroll
                    for (int nt = 0; nt < 4; nt++) {
                        mma_bf16(acc[mt][nt], ah[mt], bh[nt]);
                        mma_bf16(acc[mt][nt], ah[mt], bl[nt]);
                        mma_bf16(acc[mt][nt], al[mt], bh[nt]);
                    }
            }
        }
        __syncthreads();
        if (c + 1 < NCHUNK) {
            char* bp = smem + ((c + 1) & 1) * BUF_B;
            *(uint4*)(bp + 0*TILE_B + so0) = p0; *(uint4*)(bp + 0*TILE_B + so1) = p1;
            *(uint4*)(bp + 1*TILE_B + so0) = p2; *(uint4*)(bp + 1*TILE_B + so1) = p3;
            *(uint4*)(bp + 2*TILE_B + so0) = p4; *(uint4*)(bp + 2*TILE_B + so1) = p5;
            *(uint4*)(bp + 3*TILE_B + so0) = p6; *(uint4*)(bp + 3*TILE_B + so1) = p7;
            __syncthreads();
        }
        #undef GLD
    }

    // ---- epilogue: direct float2 stores
    #pragma unroll
    for (int mt = 0; mt < 4; mt++) {
        #pragma unroll
        for (int nt = 0; nt < 4; nt++) {
            const int col = n0 + wn*32 + nt*8 + (lane & 3)*2;
            const float b0 = bias[col], b1 = bias[col + 1];
            #pragma unroll
            for (int half = 0; half < 2; half++) {
                const int row = m0 + wm*64 + mt*16 + (lane >> 2) + half*8;
                float2 v;
                v.x = acc[mt][nt][2*half + 0] + b0;
                v.y = acc[mt][nt][2*half + 1] + b1;
                if (MODE == 0) {
                    *(float2*)(C + (size_t)row*DIMC + col) = v;
                } else {
                    const int which = col >> 9;          // 0=q 1=k 2=v
                    const int head  = (col & 511) >> 5;
                    const int d     = col & 31;          // even
                    float* dst = (which == 0) ? g_q : (which == 1) ? g_k : g_v;
                    if (which == 0) { v.x *= QK_SCALE; v.y *= QK_SCALE; }
                    const int b  = row / NT;
                    const int n  = row - b*NT;
                    *(float2*)(dst + ((size_t)((b*NH + head)*NT + n))*HD + d) = v;
                }
            }
        }
    }
}

// ---------------- attention (unchanged fp32 path) ------------------------------
#define SM_K    (NT*33)
#define SM_V    (2*NT*33)
#define SM_S    (3*NT*33)
#define SM_RINV (3*NT*33 + NT*NT)
#define SM_FLOATS (3*NT*33 + NT*NT + NT)

__global__ __launch_bounds__(256)
void attn_kernel(const float* __restrict__ mask) {
    extern __shared__ float sm[];
    float* qs   = sm;
    float* ks   = sm + SM_K;
    float* vs   = sm + SM_V;
    float* sc   = sm + SM_S;
    float* rinv = sm + SM_RINV;

    const int bh = blockIdx.x;
    const int b  = bh >> 4;
    const int h  = bh & 15;
    const int w  = b & (NWIN - 1);
    const float* mk = mask   + (size_t)w * NT * NT;
    const float* bi = g_bias + (size_t)h * NT * NT;
    const size_t base = (size_t)bh * NT * HD;

    const int tid = threadIdx.x;
    for (int idx = tid; idx < NT*HD; idx += 256) {
        int r = idx >> 5, c = idx & 31;
        qs[r*33 + c] = g_q[base + idx];
        ks[r*33 + c] = g_k[base + idx];
        vs[r*33 + c] = g_v[base + idx];
    }
    __syncthreads();

    const int warp = tid >> 5, lane = tid & 31;

    for (int i = warp; i < NT; i += 8) {
        float rq[32];
        #pragma unroll
        for (int kk = 0; kk < 32; kk++) rq[kk] = qs[i*33 + kk];
        for (int j = lane; j < NT; j += 32) {
            float acc = 0.f;
            #pragma unroll
            for (int kk = 0; kk < 32; kk++) acc += rq[kk] * ks[j*33 + kk];
            sc[i*NT + j] = acc + bi[i*NT + j] + mk[i*NT + j];
        }
    }
    __syncthreads();

    for (int i = warp; i < NT; i += 8) {
        float mx = -1e30f;
        for (int j = lane; j < NT; j += 32) mx = fmaxf(mx, sc[i*NT + j]);
        #pragma unroll
        for (int off = 16; off; off >>= 1)
            mx = fmaxf(mx, __shfl_xor_sync(0xffffffffu, mx, off));
        float s = 0.f;
        for (int j = lane; j < NT; j += 32) {
            float e = __expf(sc[i*NT + j] - mx);
            sc[i*NT + j] = e;
            s += e;
        }
        #pragma unroll
        for (int off = 16; off; off >>= 1)
            s += __shfl_xor_sync(0xffffffffu, s, off);
        if (lane == 0) rinv[i] = 1.f / s;
    }
    __syncthreads();

    const int bq = b * NT;
    for (int i = warp; i < NT; i += 8) {
        float acc = 0.f;
        const float* sr = sc + i*NT;
        #pragma unroll 2
        for (int j = 0; j < NT; j++) acc += sr[j] * vs[j*33 + lane];
        g_o[((size_t)(bq + i))*DIMC + h*HD + lane] = acc * rinv[i];
    }
}

// ---------------- launch --------------------------------------------------------
extern "C" void kernel_launch(void* const* d_in, const int* in_sizes, int n_in,
                              void* d_out, int out_size) {
    const float* x          = (const float*)d_in[0];
    const float* mask       = (const float*)d_in[1];
    const float* qkv_w      = (const float*)d_in[2];
    const float* qkv_b      = (const float*)d_in[3];
    const float* proj_w     = (const float*)d_in[4];
    const float* proj_b     = (const float*)d_in[5];
    const float* bias_table = (const float*)d_in[6];
    const int*   rel_index  = (const int*)  d_in[7];
    float* out = (float*)d_out;

    const int smem_attn = SM_FLOATS * (int)sizeof(float);   // ~77.6 KB
    cudaFuncSetAttribute(attn_kernel,
                         cudaFuncAttributeMaxDynamicSharedMemorySize, smem_attn);
    cudaFuncSetAttribute(gemm_mma<0>,
                         cudaFuncAttributeMaxDynamicSharedMemorySize, SMEM_GEMM);
    cudaFuncSetAttribute(gemm_mma<1>,
                         cudaFuncAttributeMaxDynamicSharedMemorySize, SMEM_GEMM);

    bias_gather_kernel<<<(NH*NT*NT + 255)/256, 256>>>(bias_table, rel_index);
    split_kernel<0><<<(MROWS*DIMC/8 + 255)/256, 256>>>(x, MROWS*DIMC/8);
    split_kernel<1><<<(3*DIMC*DIMC/8 + 255)/256, 256>>>(qkv_w, 3*DIMC*DIMC/8);
    split_kernel<2><<<(DIMC*DIMC/8 + 255)/256, 256>>>(proj_w, DIMC*DIMC/8);

    gemm_mma<1><<<dim3(3*DIMC/128, MROWS/128), 256, SMEM_GEMM>>>(qkv_b, nullptr);
    attn_kernel<<<NB*NH, 256, smem_attn>>>(mask);
    split_kernel<3><<<(MROWS*DIMC/8 + 255)/256, 256>>>(nullptr, MROWS*DIMC/8);
    gemm_mma<0><<<dim3(DIMC/128, MROWS/128), 256, SMEM_GEMM>>>(proj_b, out);
}

// round 7
// speedup vs baseline: 1.3782x; 1.0070x over previous
#include <cuda_runtime.h>
#include <cuda_bf16.h>
#include <math.h>
#include <stdint.h>

#define NB    512
#define NT    98
#define DIMC  512
#define NH    16
#define HD    32
#define NWIN  64
#define MROWS (NB*NT)                 // 50176
#define QK_SCALE 0.17677669529663687f

// ---------------- scratch (device globals; no runtime alloc) ---------------
__device__ __align__(16) __nv_bfloat16 g_xh[(size_t)MROWS*DIMC];
__device__ __align__(16) __nv_bfloat16 g_xl[(size_t)MROWS*DIMC];
__device__ __align__(16) __nv_bfloat16 g_wh[(size_t)3*DIMC*DIMC];
__device__ __align__(16) __nv_bfloat16 g_wl[(size_t)3*DIMC*DIMC];
__device__ __align__(16) __nv_bfloat16 g_ph[(size_t)DIMC*DIMC];
__device__ __align__(16) __nv_bfloat16 g_pl[(size_t)DIMC*DIMC];
__device__ __align__(16) __nv_bfloat16 g_oh[(size_t)MROWS*DIMC];
__device__ __align__(16) __nv_bfloat16 g_ol[(size_t)MROWS*DIMC];

__device__ float g_q[(size_t)NB*NH*NT*HD];
__device__ float g_k[(size_t)NB*NH*NT*HD];
__device__ float g_v[(size_t)NB*NH*NT*HD];
__device__ float g_o[(size_t)MROWS*DIMC];
__device__ float g_bias[NH*NT*NT];

// ---------------- helpers ----------------------------------------------------
__device__ __forceinline__ uint32_t smem_u32(const void* p) {
    uint32_t a;
    asm("{ .reg .u64 t; cvta.to.shared.u64 t, %1; cvt.u32.u64 %0, t; }"
        : "=r"(a) : "l"(p));
    return a;
}
__device__ __forceinline__ void ldsm_x4(uint32_t& r0, uint32_t& r1,
                                        uint32_t& r2, uint32_t& r3, uint32_t addr) {
    asm volatile("ldmatrix.sync.aligned.m8n8.x4.shared.b16 {%0,%1,%2,%3}, [%4];"
                 : "=r"(r0), "=r"(r1), "=r"(r2), "=r"(r3) : "r"(addr));
}
__device__ __forceinline__ void mma_bf16(float* c, const uint32_t* a, const uint32_t* b) {
    asm volatile(
        "mma.sync.aligned.m16n8k16.row.col.f32.bf16.bf16.f32 "
        "{%0,%1,%2,%3}, {%4,%5,%6,%7}, {%8,%9}, {%0,%1,%2,%3};"
        : "+f"(c[0]), "+f"(c[1]), "+f"(c[2]), "+f"(c[3])
        : "r"(a[0]), "r"(a[1]), "r"(a[2]), "r"(a[3]), "r"(b[0]), "r"(b[1]));
}
// byte offset inside one 128x32-bf16 tile for (row, 16B-quarter q)
__device__ __forceinline__ uint32_t sw_off(int row, int q) {
    return (uint32_t)(row * 64 + ((q ^ ((row >> 1) & 3)) << 4));
}

// ---------------- bias gather ------------------------------------------------
__global__ void bias_gather_kernel(const float* __restrict__ bt,
                                   const int* __restrict__ ri) {
    int idx = blockIdx.x * blockDim.x + threadIdx.x;
    if (idx < NH*NT*NT) {
        int h  = idx / (NT*NT);
        int ij = idx - h*(NT*NT);
        g_bias[idx] = bt[ri[ij]*NH + h];
    }
}

// ---------------- fp32 -> bf16 hi/lo split ------------------------------------
template<int DST>
__global__ void split_kernel(const float* __restrict__ src, int n8) {
    int i = blockIdx.x * blockDim.x + threadIdx.x;
    if (i >= n8) return;
    const float* s = (DST == 3) ? g_o : src;
    __nv_bfloat16 *hi, *lo;
    if (DST == 0)      { hi = g_xh; lo = g_xl; }
    else if (DST == 1) { hi = g_wh; lo = g_wl; }
    else if (DST == 2) { hi = g_ph; lo = g_pl; }
    else               { hi = g_oh; lo = g_ol; }

    float4 a = ((const float4*)s)[2*i];
    float4 b = ((const float4*)s)[2*i + 1];
    float v[8] = {a.x, a.y, a.z, a.w, b.x, b.y, b.z, b.w};
    __nv_bfloat16 h[8], l[8];
    #pragma unroll
    for (int k = 0; k < 8; k++) {
        h[k] = __float2bfloat16(v[k]);
        l[k] = __float2bfloat16(v[k] - __bfloat162float(h[k]));
    }
    __nv_bfloat162* hi2 = (__nv_bfloat162*)hi;
    __nv_bfloat162* lo2 = (__nv_bfloat162*)lo;
    #pragma unroll
    for (int k = 0; k < 4; k++) {
        hi2[4*i + k] = __halves2bfloat162(h[2*k], h[2*k+1]);
        lo2[4*i + k] = __halves2bfloat162(l[2*k], l[2*k+1]);
    }
}

// ---------------- HMMA bf16x3 GEMM --------------------------------------------
// C[M,N] = A[M,512] @ B[N,512]^T + bias[N]
// MODE 1: A=g_xh/g_xl, B=g_wh/g_wl (N=1536), scatter q/k/v
// MODE 0: A=g_oh/g_ol, B=g_ph/g_pl (N=512), plain write
#define KCH     32
#define NCHUNK  (DIMC / KCH)        // 16
#define TILE_B  8192                // 128 rows x 64B
#define BUF_B   (4 * TILE_B)        // Ah, Al, Bh, Bl
#define SMEM_GEMM (2 * BUF_B)       // 64 KB

template<int MODE>
__global__ __launch_bounds__(256)
void gemm_mma(const float* __restrict__ bias, float* __restrict__ C) {
    extern __shared__ char smem[];
    const int tid  = threadIdx.x;
    const int lane = tid & 31;
    const int wid  = tid >> 5;
    const int wm   = wid >> 2;       // 0..1 -> m offset 64*wm
    const int wn   = wid & 3;        // 0..3 -> n offset 32*wn
    const int m0 = blockIdx.y * 128;
    const int n0 = blockIdx.x * 128;

    const __nv_bfloat16* Ah = (MODE == 1) ? g_xh : g_oh;
    const __nv_bfloat16* Al = (MODE == 1) ? g_xl : g_ol;
    const __nv_bfloat16* Bh = (MODE == 1) ? g_wh : g_ph;
    const __nv_bfloat16* Bl = (MODE == 1) ? g_wl : g_pl;

    const uint32_t sb = smem_u32(smem);

    // fill mapping: thread covers rows {r, r+64}, fixed 16B quarter q
    const int frow = tid >> 2;       // 0..63
    const int fq   = tid & 3;        // 0..3
    const uint32_t so0 = sw_off(frow,      fq);
    const uint32_t so1 = sw_off(frow + 64, fq);

    float acc[4][4][4];
    #pragma unroll
    for (int i = 0; i < 4; i++)
        #pragma unroll
        for (int j = 0; j < 4; j++)
            #pragma unroll
            for (int k = 0; k < 4; k++) acc[i][j][k] = 0.f;

    // ---- chunk 0 fill
    {
        char* bp = smem;
        #define GLD(P, RB, ROW, K0) (*(const uint4*)((P) + (size_t)((RB)+(ROW))*DIMC + (K0) + fq*8))
        uint4 p0 = GLD(Ah, m0, frow, 0), p1 = GLD(Ah, m0, frow+64, 0);
        uint4 p2 = GLD(Al, m0, frow, 0), p3 = GLD(Al, m0, frow+64, 0);
        uint4 p4 = GLD(Bh, n0, frow, 0), p5 = GLD(Bh, n0, frow+64, 0);
        uint4 p6 = GLD(Bl, n0, frow, 0), p7 = GLD(Bl, n0, frow+64, 0);
        *(uint4*)(bp + 0*TILE_B + so0) = p0; *(uint4*)(bp + 0*TILE_B + so1) = p1;
        *(uint4*)(bp + 1*TILE_B + so0) = p2; *(uint4*)(bp + 1*TILE_B + so1) = p3;
        *(uint4*)(bp + 2*TILE_B + so0) = p4; *(uint4*)(bp + 2*TILE_B + so1) = p5;
        *(uint4*)(bp + 3*TILE_B + so0) = p6; *(uint4*)(bp + 3*TILE_B + so1) = p7;
    }
    __syncthreads();

    const int lr  = lane & 15;
    const int lq2 = lane >> 4;

    for (int c = 0; c < NCHUNK; c++) {
        uint4 p0, p1, p2, p3, p4, p5, p6, p7;
        if (c + 1 < NCHUNK) {
            const int k0 = (c + 1) * KCH;
            p0 = GLD(Ah, m0, frow, k0); p1 = GLD(Ah, m0, frow+64, k0);
            p2 = GLD(Al, m0, frow, k0); p3 = GLD(Al, m0, frow+64, k0);
            p4 = GLD(Bh, n0, frow, k0); p5 = GLD(Bh, n0, frow+64, k0);
            p6 = GLD(Bl, n0, frow, k0); p7 = GLD(Bl, n0, frow+64, k0);
        }
        // ---- compute on buffer c&1
        {
            const uint32_t tba = sb + (uint32_t)(c & 1) * BUF_B;
            #pragma unroll
            for (int ks = 0; ks < 2; ks++) {
                uint32_t ah[4][4], al[4][4], bh[4][2], bl[4][2];
                #pragma unroll
                for (int mt = 0; mt < 4; mt++) {
                    int r = wm*64 + mt*16 + lr;
                    uint32_t off = sw_off(r, 2*ks + lq2);
                    ldsm_x4(ah[mt][0], ah[mt][1], ah[mt][2], ah[mt][3], tba + off);
                    ldsm_x4(al[mt][0], al[mt][1], al[mt][2], al[mt][3], tba + TILE_B + off);
                }
                #pragma unroll
                for (int g2 = 0; g2 < 2; g2++) {
                    int r = wn*32 + g2*16 + lr;
                    uint32_t off = sw_off(r, 2*ks + lq2);
                    uint32_t t0, t1, t2, t3;
                    ldsm_x4(t0, t1, t2, t3, tba + 2*TILE_B + off);
                    bh[2*g2][0] = t0; bh[2*g2][1] = t2;
                    bh[2*g2+1][0] = t1; bh[2*g2+1][1] = t3;
                    ldsm_x4(t0, t1, t2, t3, tba + 3*TILE_B + off);
                    bl[2*g2][0] = t0; bl[2*g2][1] = t2;
                    bl[2*g2+1][0] = t1; bl[2*g2+1][1] = t3;
                }
                #pragma unroll
                for (int mt = 0; mt < 4; mt++)
                    #pragma unroll
                    for (int nt = 0; nt < 4; nt++) {
                        mma_bf16(acc[mt][nt], ah[mt], bh[nt]);
                        mma_bf16(acc[mt][nt], ah[mt], bl[nt]);
                        mma_bf16(acc[mt][nt], al[mt], bh[nt]);
                    }
            }
        }
        __syncthreads();
        if (c + 1 < NCHUNK) {
            char* bp = smem + ((c + 1) & 1) * BUF_B;
            *(uint4*)(bp + 0*TILE_B + so0) = p0; *(uint4*)(bp + 0*TILE_B + so1) = p1;
            *(uint4*)(bp + 1*TILE_B + so0) = p2; *(uint4*)(bp + 1*TILE_B + so1) = p3;
            *(uint4*)(bp + 2*TILE_B + so0) = p4; *(uint4*)(bp + 2*TILE_B + so1) = p5;
            *(uint4*)(bp + 3*TILE_B + so0) = p6; *(uint4*)(bp + 3*TILE_B + so1) = p7;
            __syncthreads();
        }
        #undef GLD
    }

    // ---- epilogue: direct float2 stores
    #pragma unroll
    for (int mt = 0; mt < 4; mt++) {
        #pragma unroll
        for (int nt = 0; nt < 4; nt++) {
            const int col = n0 + wn*32 + nt*8 + (lane & 3)*2;
            const float b0 = bias[col], b1 = bias[col + 1];
            #pragma unroll
            for (int half = 0; half < 2; half++) {
                const int row = m0 + wm*64 + mt*16 + (lane >> 2) + half*8;
                float2 v;
                v.x = acc[mt][nt][2*half + 0] + b0;
                v.y = acc[mt][nt][2*half + 1] + b1;
                if (MODE == 0) {
                    *(float2*)(C + (size_t)row*DIMC + col) = v;
                } else {
                    const int which = col >> 9;          // 0=q 1=k 2=v
                    const int head  = (col & 511) >> 5;
                    const int d     = col & 31;          // even
                    float* dst = (which == 0) ? g_q : (which == 1) ? g_k : g_v;
                    if (which == 0) { v.x *= QK_SCALE; v.y *= QK_SCALE; }
                    const int b  = row / NT;
                    const int n  = row - b*NT;
                    *(float2*)(dst + ((size_t)((b*NH + head)*NT + n))*HD + d) = v;
                }
            }
        }
    }
}

// ---------------- attention (unchanged fp32 path) ------------------------------
#define SM_K    (NT*33)
#define SM_V    (2*NT*33)
#define SM_S    (3*NT*33)
#define SM_RINV (3*NT*33 + NT*NT)
#define SM_FLOATS (3*NT*33 + NT*NT + NT)

__global__ __launch_bounds__(256)
void attn_kernel(const float* __restrict__ mask) {
    extern __shared__ float sm[];
    float* qs   = sm;
    float* ks   = sm + SM_K;
    float* vs   = sm + SM_V;
    float* sc   = sm + SM_S;
    float* rinv = sm + SM_RINV;

    const int bh = blockIdx.x;
    const int b  = bh >> 4;
    const int h  = bh & 15;
    const int w  = b & (NWIN - 1);
    const float* mk = mask   + (size_t)w * NT * NT;
    const float* bi = g_bias + (size_t)h * NT * NT;
    const size_t base = (size_t)bh * NT * HD;

    const int tid = threadIdx.x;
    for (int idx = tid; idx < NT*HD; idx += 256) {
        int r = idx >> 5, c = idx & 31;
        qs[r*33 + c] = g_q[base + idx];
        ks[r*33 + c] = g_k[base + idx];
        vs[r*33 + c] = g_v[base + idx];
    }
    __syncthreads();

    const int warp = tid >> 5, lane = tid & 31;

    for (int i = warp; i < NT; i += 8) {
        float rq[32];
        #pragma unroll
        for (int kk = 0; kk < 32; kk++) rq[kk] = qs[i*33 + kk];
        for (int j = lane; j < NT; j += 32) {
            float acc = 0.f;
            #pragma unroll
            for (int kk = 0; kk < 32; kk++) acc += rq[kk] * ks[j*33 + kk];
            sc[i*NT + j] = acc + bi[i*NT + j] + mk[i*NT + j];
        }
    }
    __syncthreads();

    for (int i = warp; i < NT; i += 8) {
        float mx = -1e30f;
        for (int j = lane; j < NT; j += 32) mx = fmaxf(mx, sc[i*NT + j]);
        #pragma unroll
        for (int off = 16; off; off >>= 1)
            mx = fmaxf(mx, __shfl_xor_sync(0xffffffffu, mx, off));
        float s = 0.f;
        for (int j = lane; j < NT; j += 32) {
            float e = __expf(sc[i*NT + j] - mx);
            sc[i*NT + j] = e;
            s += e;
        }
        #pragma unroll
        for (int off = 16; off; off >>= 1)
            s += __shfl_xor_sync(0xffffffffu, s, off);
        if (lane == 0) rinv[i] = 1.f / s;
    }
    __syncthreads();

    const int bq = b * NT;
    for (int i = warp; i < NT; i += 8) {
        float acc = 0.f;
        const float* sr = sc + i*NT;
        #pragma unroll 2
        for (int j = 0; j < NT; j++) acc += sr[j] * vs[j*33 + lane];
        g_o[((size_t)(bq + i))*DIMC + h*HD + lane] = acc * rinv[i];
    }
}

// ---------------- launch --------------------------------------------------------
extern "C" void kernel_launch(void* const* d_in, const int* in_sizes, int n_in,
                              void* d_out, int out_size) {
    const float* x          = (const float*)d_in[0];
    const float* mask       = (const float*)d_in[1];
    const float* qkv_w      = (const float*)d_in[2];
    const float* qkv_b      = (const float*)d_in[3];
    const float* proj_w     = (const float*)d_in[4];
    const float* proj_b     = (const float*)d_in[5];
    const float* bias_table = (const float*)d_in[6];
    const int*   rel_index  = (const int*)  d_in[7];
    float* out = (float*)d_out;

    const int smem_attn = SM_FLOATS * (int)sizeof(float);   // ~77.6 KB
    cudaFuncSetAttribute(attn_kernel,
                         cudaFuncAttributeMaxDynamicSharedMemorySize, smem_attn);
    cudaFuncSetAttribute(gemm_mma<0>,
                         cudaFuncAttributeMaxDynamicSharedMemorySize, SMEM_GEMM);
    cudaFuncSetAttribute(gemm_mma<1>,
                         cudaFuncAttributeMaxDynamicSharedMemorySize, SMEM_GEMM);

    bias_gather_kernel<<<(NH*NT*NT + 255)/256, 256>>>(bias_table, rel_index);
    split_kernel<0><<<(MROWS*DIMC/8 + 255)/256, 256>>>(x, MROWS*DIMC/8);
    split_kernel<1><<<(3*DIMC*DIMC/8 + 255)/256, 256>>>(qkv_w, 3*DIMC*DIMC/8);
    split_kernel<2><<<(DIMC*DIMC/8 + 255)/256, 256>>>(proj_w, DIMC*DIMC/8);

    gemm_mma<1><<<dim3(3*DIMC/128, MROWS/128), 256, SMEM_GEMM>>>(qkv_b, nullptr);
    attn_kernel<<<NB*NH, 256, smem_attn>>>(mask);
    split_kernel<3><<<(MROWS*DIMC/8 + 255)/256, 256>>>(nullptr, MROWS*DIMC/8);
    gemm_mma<0><<<dim3(DIMC/128, MROWS/128), 256, SMEM_GEMM>>>(proj_b, out);
}

// round 8
// speedup vs baseline: 1.5970x; 1.1588x over previous
#include <cuda_runtime.h>
#include <cuda_bf16.h>
#include <math.h>
#include <stdint.h>

#define NB    512
#define NT    98
#define DIMC  512
#define NH    16
#define HD    32
#define NWIN  64
#define MROWS (NB*NT)                 // 50176
#define QK_SCALE 0.17677669529663687f

// ---------------- scratch (device globals; no runtime alloc) ---------------
__device__ __align__(16) __nv_bfloat16 g_xh[(size_t)MROWS*DIMC];
__device__ __align__(16) __nv_bfloat16 g_xl[(size_t)MROWS*DIMC];
__device__ __align__(16) __nv_bfloat16 g_wh[(size_t)3*DIMC*DIMC];
__device__ __align__(16) __nv_bfloat16 g_wl[(size_t)3*DIMC*DIMC];
__device__ __align__(16) __nv_bfloat16 g_ph[(size_t)DIMC*DIMC];
__device__ __align__(16) __nv_bfloat16 g_pl[(size_t)DIMC*DIMC];
__device__ __align__(16) __nv_bfloat16 g_oh[(size_t)MROWS*DIMC];
__device__ __align__(16) __nv_bfloat16 g_ol[(size_t)MROWS*DIMC];

// q/k/v as bf16 hi/lo, layout [(b*NH+h)*NT + n][HD]
__device__ __align__(16) __nv_bfloat16 g_qh[(size_t)NB*NH*NT*HD];
__device__ __align__(16) __nv_bfloat16 g_ql[(size_t)NB*NH*NT*HD];
__device__ __align__(16) __nv_bfloat16 g_kh[(size_t)NB*NH*NT*HD];
__device__ __align__(16) __nv_bfloat16 g_kl[(size_t)NB*NH*NT*HD];
__device__ __align__(16) __nv_bfloat16 g_vh[(size_t)NB*NH*NT*HD];
__device__ __align__(16) __nv_bfloat16 g_vl[(size_t)NB*NH*NT*HD];

__device__ float g_bias[NH*NT*NT];

// ---------------- helpers ----------------------------------------------------
__device__ __forceinline__ uint32_t smem_u32(const void* p) {
    uint32_t a;
    asm("{ .reg .u64 t; cvta.to.shared.u64 t, %1; cvt.u32.u64 %0, t; }"
        : "=r"(a) : "l"(p));
    return a;
}
__device__ __forceinline__ void ldsm_x4(uint32_t& r0, uint32_t& r1,
                                        uint32_t& r2, uint32_t& r3, uint32_t addr) {
    asm volatile("ldmatrix.sync.aligned.m8n8.x4.shared.b16 {%0,%1,%2,%3}, [%4];"
                 : "=r"(r0), "=r"(r1), "=r"(r2), "=r"(r3) : "r"(addr));
}
__device__ __forceinline__ void ldsm_x4_t(uint32_t& r0, uint32_t& r1,
                                          uint32_t& r2, uint32_t& r3, uint32_t addr) {
    asm volatile("ldmatrix.sync.aligned.m8n8.x4.trans.shared.b16 {%0,%1,%2,%3}, [%4];"
                 : "=r"(r0), "=r"(r1), "=r"(r2), "=r"(r3) : "r"(addr));
}
__device__ __forceinline__ void mma_bf16(float* c, const uint32_t* a, const uint32_t* b) {
    asm volatile(
        "mma.sync.aligned.m16n8k16.row.col.f32.bf16.bf16.f32 "
        "{%0,%1,%2,%3}, {%4,%5,%6,%7}, {%8,%9}, {%0,%1,%2,%3};"
        : "+f"(c[0]), "+f"(c[1]), "+f"(c[2]), "+f"(c[3])
        : "r"(a[0]), "r"(a[1]), "r"(a[2]), "r"(a[3]), "r"(b[0]), "r"(b[1]));
}
// byte offset inside one [rows]x32-bf16 tile (64B rows) for (row, 16B-quarter q)
__device__ __forceinline__ uint32_t sw_off(int row, int q) {
    return (uint32_t)(row * 64 + ((q ^ ((row >> 1) & 3)) << 4));
}

// ---------------- bias gather ------------------------------------------------
__global__ void bias_gather_kernel(const float* __restrict__ bt,
                                   const int* __restrict__ ri) {
    int idx = blockIdx.x * blockDim.x + threadIdx.x;
    if (idx < NH*NT*NT) {
        int h  = idx / (NT*NT);
        int ij = idx - h*(NT*NT);
        g_bias[idx] = bt[ri[ij]*NH + h];
    }
}

// ---------------- fp32 -> bf16 hi/lo split ------------------------------------
template<int DST>
__global__ void split_kernel(const float* __restrict__ src, int n8) {
    int i = blockIdx.x * blockDim.x + threadIdx.x;
    if (i >= n8) return;
    __nv_bfloat16 *hi, *lo;
    if (DST == 0)      { hi = g_xh; lo = g_xl; }
    else if (DST == 1) { hi = g_wh; lo = g_wl; }
    else               { hi = g_ph; lo = g_pl; }

    float4 a = ((const float4*)src)[2*i];
    float4 b = ((const float4*)src)[2*i + 1];
    float v[8] = {a.x, a.y, a.z, a.w, b.x, b.y, b.z, b.w};
    __nv_bfloat16 h[8], l[8];
    #pragma unroll
    for (int k = 0; k < 8; k++) {
        h[k] = __float2bfloat16(v[k]);
        l[k] = __float2bfloat16(v[k] - __bfloat162float(h[k]));
    }
    __nv_bfloat162* hi2 = (__nv_bfloat162*)hi;
    __nv_bfloat162* lo2 = (__nv_bfloat162*)lo;
    #pragma unroll
    for (int k = 0; k < 4; k++) {
        hi2[4*i + k] = __halves2bfloat162(h[2*k], h[2*k+1]);
        lo2[4*i + k] = __halves2bfloat162(l[2*k], l[2*k+1]);
    }
}

// ---------------- HMMA bf16x3 GEMM --------------------------------------------
// C[M,N] = A[M,512] @ B[N,512]^T + bias[N]
// MODE 1: A=g_xh/g_xl, B=g_wh/g_wl (N=1536), scatter q/k/v as bf16 hi/lo
// MODE 0: A=g_oh/g_ol, B=g_ph/g_pl (N=512), plain fp32 write
#define KCH     32
#define NCHUNK  (DIMC / KCH)        // 16
#define TILE_B  8192                // 128 rows x 64B
#define BUF_B   (4 * TILE_B)        // Ah, Al, Bh, Bl
#define SMEM_GEMM (2 * BUF_B)       // 64 KB

template<int MODE>
__global__ __launch_bounds__(256)
void gemm_mma(const float* __restrict__ bias, float* __restrict__ C) {
    extern __shared__ char smem[];
    const int tid  = threadIdx.x;
    const int lane = tid & 31;
    const int wid  = tid >> 5;
    const int wm   = wid >> 2;
    const int wn   = wid & 3;
    const int m0 = blockIdx.y * 128;
    const int n0 = blockIdx.x * 128;

    const __nv_bfloat16* Ah = (MODE == 1) ? g_xh : g_oh;
    const __nv_bfloat16* Al = (MODE == 1) ? g_xl : g_ol;
    const __nv_bfloat16* Bh = (MODE == 1) ? g_wh : g_ph;
    const __nv_bfloat16* Bl = (MODE == 1) ? g_wl : g_pl;

    const uint32_t sb = smem_u32(smem);

    const int frow = tid >> 2;
    const int fq   = tid & 3;
    const uint32_t so0 = sw_off(frow,      fq);
    const uint32_t so1 = sw_off(frow + 64, fq);

    float acc[4][4][4];
    #pragma unroll
    for (int i = 0; i < 4; i++)
        #pragma unroll
        for (int j = 0; j < 4; j++)
            #pragma unroll
            for (int k = 0; k < 4; k++) acc[i][j][k] = 0.f;

    {
        char* bp = smem;
        #define GLD(P, RB, ROW, K0) (*(const uint4*)((P) + (size_t)((RB)+(ROW))*DIMC + (K0) + fq*8))
        uint4 p0 = GLD(Ah, m0, frow, 0), p1 = GLD(Ah, m0, frow+64, 0);
        uint4 p2 = GLD(Al, m0, frow, 0), p3 = GLD(Al, m0, frow+64, 0);
        uint4 p4 = GLD(Bh, n0, frow, 0), p5 = GLD(Bh, n0, frow+64, 0);
        uint4 p6 = GLD(Bl, n0, frow, 0), p7 = GLD(Bl, n0, frow+64, 0);
        *(uint4*)(bp + 0*TILE_B + so0) = p0; *(uint4*)(bp + 0*TILE_B + so1) = p1;
        *(uint4*)(bp + 1*TILE_B + so0) = p2; *(uint4*)(bp + 1*TILE_B + so1) = p3;
        *(uint4*)(bp + 2*TILE_B + so0) = p4; *(uint4*)(bp + 2*TILE_B + so1) = p5;
        *(uint4*)(bp + 3*TILE_B + so0) = p6; *(uint4*)(bp + 3*TILE_B + so1) = p7;
    }
    __syncthreads();

    const int lr  = lane & 15;
    const int lq2 = lane >> 4;

    for (int c = 0; c < NCHUNK; c++) {
        uint4 p0, p1, p2, p3, p4, p5, p6, p7;
        if (c + 1 < NCHUNK) {
            const int k0 = (c + 1) * KCH;
            p0 = GLD(Ah, m0, frow, k0); p1 = GLD(Ah, m0, frow+64, k0);
            p2 = GLD(Al, m0, frow, k0); p3 = GLD(Al, m0, frow+64, k0);
            p4 = GLD(Bh, n0, frow, k0); p5 = GLD(Bh, n0, frow+64, k0);
            p6 = GLD(Bl, n0, frow, k0); p7 = GLD(Bl, n0, frow+64, k0);
        }
        {
            const uint32_t tba = sb + (uint32_t)(c & 1) * BUF_B;
            #pragma unroll
            for (int ks = 0; ks < 2; ks++) {
                uint32_t ah[4][4], al[4][4], bh[4][2], bl[4][2];
                #pragma unroll
                for (int mt = 0; mt < 4; mt++) {
                    int r = wm*64 + mt*16 + lr;
                    uint32_t off = sw_off(r, 2*ks + lq2);
                    ldsm_x4(ah[mt][0], ah[mt][1], ah[mt][2], ah[mt][3], tba + off);
                    ldsm_x4(al[mt][0], al[mt][1], al[mt][2], al[mt][3], tba + TILE_B + off);
                }
                #pragma unroll
                for (int g2 = 0; g2 < 2; g2++) {
                    int r = wn*32 + g2*16 + lr;
                    uint32_t off = sw_off(r, 2*ks + lq2);
                    uint32_t t0, t1, t2, t3;
                    ldsm_x4(t0, t1, t2, t3, tba + 2*TILE_B + off);
                    bh[2*g2][0] = t0; bh[2*g2][1] = t2;
                    bh[2*g2+1][0] = t1; bh[2*g2+1][1] = t3;
                    ldsm_x4(t0, t1, t2, t3, tba + 3*TILE_B + off);
                    bl[2*g2][0] = t0; bl[2*g2][1] = t2;
                    bl[2*g2+1][0] = t1; bl[2*g2+1][1] = t3;
                }
                #pragma unroll
                for (int mt = 0; mt < 4; mt++)
                    #pragma unroll
                    for (int nt = 0; nt < 4; nt++) {
                        mma_bf16(acc[mt][nt], ah[mt], bh[nt]);
                        mma_bf16(acc[mt][nt], ah[mt], bl[nt]);
                        mma_bf16(acc[mt][nt], al[mt], bh[nt]);
                    }
            }
        }
        __syncthreads();
        if (c + 1 < NCHUNK) {
            char* bp = smem + ((c + 1) & 1) * BUF_B;
            *(uint4*)(bp + 0*TILE_B + so0) = p0; *(uint4*)(bp + 0*TILE_B + so1) = p1;
            *(uint4*)(bp + 1*TILE_B + so0) = p2; *(uint4*)(bp + 1*TILE_B + so1) = p3;
            *(uint4*)(bp + 2*TILE_B + so0) = p4; *(uint4*)(bp + 2*TILE_B + so1) = p5;
            *(uint4*)(bp + 3*TILE_B + so0) = p6; *(uint4*)(bp + 3*TILE_B + so1) = p7;
            __syncthreads();
        }
        #undef GLD
    }

    #pragma unroll
    for (int mt = 0; mt < 4; mt++) {
        #pragma unroll
        for (int nt = 0; nt < 4; nt++) {
            const int col = n0 + wn*32 + nt*8 + (lane & 3)*2;
            const float b0 = bias[col], b1 = bias[col + 1];
            #pragma unroll
            for (int half = 0; half < 2; half++) {
                const int row = m0 + wm*64 + mt*16 + (lane >> 2) + half*8;
                float2 v;
                v.x = acc[mt][nt][2*half + 0] + b0;
                v.y = acc[mt][nt][2*half + 1] + b1;
                if (MODE == 0) {
                    *(float2*)(C + (size_t)row*DIMC + col) = v;
                } else {
                    const int which = col >> 9;          // 0=q 1=k 2=v
                    const int head  = (col & 511) >> 5;
                    const int d     = col & 31;
                    __nv_bfloat16 *dh, *dl;
                    if (which == 0)      { dh = g_qh; dl = g_ql; v.x *= QK_SCALE; v.y *= QK_SCALE; }
                    else if (which == 1) { dh = g_kh; dl = g_kl; }
                    else                 { dh = g_vh; dl = g_vl; }
                    const int b = row / NT;
                    const int n = row - b*NT;
                    const size_t o = ((size_t)((b*NH + head)*NT + n))*HD + d;
                    __nv_bfloat16 h0 = __float2bfloat16(v.x);
                    __nv_bfloat16 h1 = __float2bfloat16(v.y);
                    __nv_bfloat16 l0 = __float2bfloat16(v.x - __bfloat162float(h0));
                    __nv_bfloat16 l1 = __float2bfloat16(v.y - __bfloat162float(h1));
                    *(__nv_bfloat162*)(dh + o) = __halves2bfloat162(h0, h1);
                    *(__nv_bfloat162*)(dl + o) = __halves2bfloat162(l0, l1);
                }
            }
        }
    }
}

// ---------------- HMMA attention: one block per (b,h) --------------------------
#define AP      112                 // padded token dim (7 x 16)
#define SPITCH  114                 // S fp32 pitch (floats)
#define PPITCH  136                 // P bf16 pitch (elements); 272B rows

#define AT_QH 0
#define AT_QL (AT_QH + AP*64)
#define AT_KH (AT_QL + AP*64)
#define AT_KL (AT_KH + AP*64)
#define AT_VH (AT_KL + AP*64)
#define AT_VL (AT_VH + AP*64)
#define AT_S  (AT_VL + AP*64)
#define AT_PH (AT_S  + AP*SPITCH*4)
#define AT_PL (AT_PH + AP*PPITCH*2)
#define AT_BYTES (AT_PL + AP*PPITCH*2)   // 155008

__global__ __launch_bounds__(256)
void attn_mma_kernel(const float* __restrict__ mask) {
    extern __shared__ char sm[];
    const int tid  = threadIdx.x;
    const int lane = tid & 31;
    const int wid  = tid >> 5;
    const int bh = blockIdx.x;
    const int b  = bh >> 4;
    const int h  = bh & 15;
    const int w  = b & (NWIN - 1);
    const uint32_t sb = smem_u32(sm);

    // ---- fill q/k/v hi/lo tiles (zero pad rows 98..111)
    {
        const __nv_bfloat16* gsrc[6] = { g_qh, g_ql, g_kh, g_kl, g_vh, g_vl };
        const size_t gbase = (size_t)bh * (NT*HD);
        for (int c = tid; c < 6*AP*4; c += 256) {
            int mat = c / (AP*4);
            int rem = c % (AP*4);
            int row = rem >> 2, q = rem & 3;
            uint4 val = make_uint4(0, 0, 0, 0);
            if (row < NT)
                val = *(const uint4*)(gsrc[mat] + gbase + (size_t)row*HD + q*8);
            *(uint4*)(sm + mat*AP*64 + sw_off(row, q)) = val;
        }
        // zero P pad rows 98..111 (both planes)
        for (int c = tid; c < 2*14*68; c += 256) {
            int plane = c / (14*68);
            int rem   = c % (14*68);
            int row   = NT + rem / 68;
            int wd    = rem % 68;
            *(uint32_t*)(sm + (plane ? AT_PL : AT_PH) + row*272 + wd*4) = 0;
        }
    }
    __syncthreads();

    const int lr  = lane & 15;
    const int lq2 = lane >> 4;
    float* S = (float*)(sm + AT_S);

    // ---- S = Q K^T (bf16 hi/lo x3)
    for (int pos = wid; pos < 49; pos += 8) {
        int mt = pos / 7, nt = pos % 7;
        uint32_t ah[2][4], al[2][4], kh[2][2][2], kl[2][2][2];
        #pragma unroll
        for (int ks = 0; ks < 2; ks++) {
            uint32_t offa = sw_off(mt*16 + lr, 2*ks + lq2);
            ldsm_x4(ah[ks][0], ah[ks][1], ah[ks][2], ah[ks][3], sb + AT_QH + offa);
            ldsm_x4(al[ks][0], al[ks][1], al[ks][2], al[ks][3], sb + AT_QL + offa);
            uint32_t offb = sw_off(nt*16 + lr, 2*ks + lq2);
            uint32_t t0, t1, t2, t3;
            ldsm_x4(t0, t1, t2, t3, sb + AT_KH + offb);
            kh[ks][0][0] = t0; kh[ks][0][1] = t2;
            kh[ks][1][0] = t1; kh[ks][1][1] = t3;
            ldsm_x4(t0, t1, t2, t3, sb + AT_KL + offb);
            kl[ks][0][0] = t0; kl[ks][0][1] = t2;
            kl[ks][1][0] = t1; kl[ks][1][1] = t3;
        }
        float c[2][4] = {};
        #pragma unroll
        for (int ks = 0; ks < 2; ks++)
            #pragma unroll
            for (int n8 = 0; n8 < 2; n8++) {
                mma_bf16(c[n8], ah[ks], kh[ks][n8]);
                mma_bf16(c[n8], ah[ks], kl[ks][n8]);
                mma_bf16(c[n8], al[ks], kh[ks][n8]);
            }
        #pragma unroll
        for (int n8 = 0; n8 < 2; n8++)
            #pragma unroll
            for (int half = 0; half < 2; half++) {
                int row = mt*16 + (lane >> 2) + half*8;
                int col = nt*16 + n8*8 + (lane & 3)*2;
                *(float2*)&S[row*SPITCH + col] =
                    make_float2(c[n8][2*half], c[n8][2*half + 1]);
            }
    }
    __syncthreads();

    // ---- softmax (fused bias+mask), write normalized P as bf16 hi/lo
    {
        const float* bi = g_bias + (size_t)h * (NT*NT);
        const float* mk = mask   + (size_t)w * (NT*NT);
        __nv_bfloat16* Ph = (__nv_bfloat16*)(sm + AT_PH);
        __nv_bfloat16* Pl = (__nv_bfloat16*)(sm + AT_PL);
        for (int i = wid; i < NT; i += 8) {
            float t[4];
            #pragma unroll
            for (int r = 0; r < 4; r++) {
                int j = lane + 32*r;
                t[r] = (j < NT) ? S[i*SPITCH + j] + bi[i*NT + j] + mk[i*NT + j]
                                : -1e30f;
            }
            float mx = fmaxf(fmaxf(t[0], t[1]), fmaxf(t[2], t[3]));
            #pragma unroll
            for (int off = 16; off; off >>= 1)
                mx = fmaxf(mx, __shfl_xor_sync(0xffffffffu, mx, off));
            float e[4], s = 0.f;
            #pragma unroll
            for (int r = 0; r < 4; r++) {
                int j = lane + 32*r;
                e[r] = (j < NT) ? __expf(t[r] - mx) : 0.f;
                s += e[r];
            }
            #pragma unroll
            for (int off = 16; off; off >>= 1)
                s += __shfl_xor_sync(0xffffffffu, s, off);
            float rinv = 1.f / s;
            #pragma unroll
            for (int r = 0; r < 4; r++) {
                int j = lane + 32*r;       // <= 127 < PPITCH
                float p = e[r] * rinv;
                __nv_bfloat16 ph = __float2bfloat16(p);
                __nv_bfloat16 pl = __float2bfloat16(p - __bfloat162float(ph));
                Ph[i*PPITCH + j] = ph;
                Pl[i*PPITCH + j] = pl;
            }
        }
    }
    __syncthreads();

    // ---- out = P V (bf16 hi/lo x3), write g_oh/g_ol directly
    for (int pos = wid; pos < 14; pos += 8) {
        int mt = pos >> 1, nt = pos & 1;
        float c[2][4] = {};
        for (int kt = 0; kt < 7; kt++) {
            uint32_t pa[4], pb[4];
            uint32_t offp = (uint32_t)(mt*16 + lr)*272 + (uint32_t)(kt*2 + lq2)*16;
            ldsm_x4(pa[0], pa[1], pa[2], pa[3], sb + AT_PH + offp);
            ldsm_x4(pb[0], pb[1], pb[2], pb[3], sb + AT_PL + offp);
            uint32_t offv = sw_off(kt*16 + lr, nt*2 + lq2);
            uint32_t t0, t1, t2, t3;
            ldsm_x4_t(t0, t1, t2, t3, sb + AT_VH + offv);
            uint32_t vh0[2] = {t0, t1}, vh1[2] = {t2, t3};
            ldsm_x4_t(t0, t1, t2, t3, sb + AT_VL + offv);
            uint32_t vl0[2] = {t0, t1}, vl1[2] = {t2, t3};
            mma_bf16(c[0], pa, vh0);
            mma_bf16(c[0], pa, vl0);
            mma_bf16(c[0], pb, vh0);
            mma_bf16(c[1], pa, vh1);
            mma_bf16(c[1], pa, vl1);
            mma_bf16(c[1], pb, vh1);
        }
        #pragma unroll
        for (int n8 = 0; n8 < 2; n8++)
            #pragma unroll
            for (int half = 0; half < 2; half++) {
                int i = mt*16 + (lane >> 2) + half*8;
                if (i < NT) {
                    int d = nt*16 + n8*8 + (lane & 3)*2;
                    float v0 = c[n8][2*half], v1 = c[n8][2*half + 1];
                    __nv_bfloat16 h0 = __float2bfloat16(v0);
                    __nv_bfloat16 h1 = __float2bfloat16(v1);
                    __nv_bfloat16 l0 = __float2bfloat16(v0 - __bfloat162float(h0));
                    __nv_bfloat16 l1 = __float2bfloat16(v1 - __bfloat162float(h1));
                    size_t o = (size_t)(b*NT + i)*DIMC + h*HD + d;
                    *(__nv_bfloat162*)(g_oh + o) = __halves2bfloat162(h0, h1);
                    *(__nv_bfloat162*)(g_ol + o) = __halves2bfloat162(l0, l1);
                }
            }
    }
}

// ---------------- launch --------------------------------------------------------
extern "C" void kernel_launch(void* const* d_in, const int* in_sizes, int n_in,
                              void* d_out, int out_size) {
    const float* x          = (const float*)d_in[0];
    const float* mask       = (const float*)d_in[1];
    const float* qkv_w      = (const float*)d_in[2];
    const float* qkv_b      = (const float*)d_in[3];
    const float* proj_w     = (const float*)d_in[4];
    const float* proj_b     = (const float*)d_in[5];
    const float* bias_table = (const float*)d_in[6];
    const int*   rel_index  = (const int*)  d_in[7];
    float* out = (float*)d_out;

    cudaFuncSetAttribute(attn_mma_kernel,
                         cudaFuncAttributeMaxDynamicSharedMemorySize, AT_BYTES);
    cudaFuncSetAttribute(gemm_mma<0>,
                         cudaFuncAttributeMaxDynamicSharedMemorySize, SMEM_GEMM);
    cudaFuncSetAttribute(gemm_mma<1>,
                         cudaFuncAttributeMaxDynamicSharedMemorySize, SMEM_GEMM);

    bias_gather_kernel<<<(NH*NT*NT + 255)/256, 256>>>(bias_table, rel_index);
    split_kernel<0><<<(MROWS*DIMC/8 + 255)/256, 256>>>(x, MROWS*DIMC/8);
    split_kernel<1><<<(3*DIMC*DIMC/8 + 255)/256, 256>>>(qkv_w, 3*DIMC*DIMC/8);
    split_kernel<2><<<(DIMC*DIMC/8 + 255)/256, 256>>>(proj_w, DIMC*DIMC/8);

    gemm_mma<1><<<dim3(3*DIMC/128, MROWS/128), 256, SMEM_GEMM>>>(qkv_b, nullptr);
    attn_mma_kernel<<<NB*NH, 256, AT_BYTES>>>(mask);
    gemm_mma<0><<<dim3(DIMC/128, MROWS/128), 256, SMEM_GEMM>>>(proj_b, out);
}

// round 9
// speedup vs baseline: 2.8777x; 1.8020x over previous
#include <cuda_runtime.h>
#include <cuda_fp16.h>
#include <math.h>
#include <stdint.h>

#define NB    512
#define NT    98
#define DIMC  512
#define NH    16
#define HD    32
#define NWIN  64
#define MROWS (NB*NT)                 // 50176
#define QK_SCALE 0.17677669529663687f

// ---------------- scratch (device globals; no runtime alloc) ---------------
__device__ __align__(16) __half g_xh[(size_t)MROWS*DIMC];
__device__ __align__(16) __half g_xl[(size_t)MROWS*DIMC];
__device__ __align__(16) __half g_w [(size_t)3*DIMC*DIMC];   // qkv_w single fp16
__device__ __align__(16) __half g_p [(size_t)DIMC*DIMC];     // proj_w single fp16
__device__ __align__(16) __half g_oh[(size_t)MROWS*DIMC];
__device__ __align__(16) __half g_ol[(size_t)MROWS*DIMC];

// q/k/v hi/lo fp16, layout [(b*NH+h)*NT + n][HD]
__device__ __align__(16) __half g_qh[(size_t)NB*NH*NT*HD];
__device__ __align__(16) __half g_ql[(size_t)NB*NH*NT*HD];
__device__ __align__(16) __half g_kh[(size_t)NB*NH*NT*HD];
__device__ __align__(16) __half g_kl[(size_t)NB*NH*NT*HD];
__device__ __align__(16) __half g_vh[(size_t)NB*NH*NT*HD];
__device__ __align__(16) __half g_vl[(size_t)NB*NH*NT*HD];

__device__ float g_bias[NH*NT*NT];

// ---------------- helpers ----------------------------------------------------
__device__ __forceinline__ uint32_t smem_u32(const void* p) {
    uint32_t a;
    asm("{ .reg .u64 t; cvta.to.shared.u64 t, %1; cvt.u32.u64 %0, t; }"
        : "=r"(a) : "l"(p));
    return a;
}
__device__ __forceinline__ void ldsm_x4(uint32_t& r0, uint32_t& r1,
                                        uint32_t& r2, uint32_t& r3, uint32_t addr) {
    asm volatile("ldmatrix.sync.aligned.m8n8.x4.shared.b16 {%0,%1,%2,%3}, [%4];"
                 : "=r"(r0), "=r"(r1), "=r"(r2), "=r"(r3) : "r"(addr));
}
__device__ __forceinline__ void ldsm_x4_t(uint32_t& r0, uint32_t& r1,
                                          uint32_t& r2, uint32_t& r3, uint32_t addr) {
    asm volatile("ldmatrix.sync.aligned.m8n8.x4.trans.shared.b16 {%0,%1,%2,%3}, [%4];"
                 : "=r"(r0), "=r"(r1), "=r"(r2), "=r"(r3) : "r"(addr));
}
__device__ __forceinline__ void mma_f16(float* c, const uint32_t* a, const uint32_t* b) {
    asm volatile(
        "mma.sync.aligned.m16n8k16.row.col.f32.f16.f16.f32 "
        "{%0,%1,%2,%3}, {%4,%5,%6,%7}, {%8,%9}, {%0,%1,%2,%3};"
        : "+f"(c[0]), "+f"(c[1]), "+f"(c[2]), "+f"(c[3])
        : "r"(a[0]), "r"(a[1]), "r"(a[2]), "r"(a[3]), "r"(b[0]), "r"(b[1]));
}
// byte offset in a [rows]x32-fp16 tile (64B rows) for (row, 16B-quarter q)
__device__ __forceinline__ uint32_t sw_off(int row, int q) {
    return (uint32_t)(row * 64 + ((q ^ ((row >> 1) & 3)) << 4));
}

// ---------------- bias gather ------------------------------------------------
__global__ void bias_gather_kernel(const float* __restrict__ bt,
                                   const int* __restrict__ ri) {
    int idx = blockIdx.x * blockDim.x + threadIdx.x;
    if (idx < NH*NT*NT) {
        int h  = idx / (NT*NT);
        int ij = idx - h*(NT*NT);
        g_bias[idx] = bt[ri[ij]*NH + h];
    }
}

// ---------------- fp32 -> fp16 hi/lo split (x) --------------------------------
__global__ void split_x_kernel(const float* __restrict__ src, int n8) {
    int i = blockIdx.x * blockDim.x + threadIdx.x;
    if (i >= n8) return;
    float4 a = ((const float4*)src)[2*i];
    float4 b = ((const float4*)src)[2*i + 1];
    float v[8] = {a.x, a.y, a.z, a.w, b.x, b.y, b.z, b.w};
    __half h[8], l[8];
    #pragma unroll
    for (int k = 0; k < 8; k++) {
        h[k] = __float2half_rn(v[k]);
        l[k] = __float2half_rn(v[k] - __half2float(h[k]));
    }
    __half2* hi2 = (__half2*)g_xh;
    __half2* lo2 = (__half2*)g_xl;
    #pragma unroll
    for (int k = 0; k < 4; k++) {
        hi2[4*i + k] = __halves2half2(h[2*k], h[2*k+1]);
        lo2[4*i + k] = __halves2half2(l[2*k], l[2*k+1]);
    }
}

// ---------------- fp32 -> fp16 single convert (weights) -----------------------
template<int DST>   // 0 -> g_w, 1 -> g_p
__global__ void cvt_kernel(const float* __restrict__ src, int n8) {
    int i = blockIdx.x * blockDim.x + threadIdx.x;
    if (i >= n8) return;
    float4 a = ((const float4*)src)[2*i];
    float4 b = ((const float4*)src)[2*i + 1];
    __half2* dst = (__half2*)((DST == 0) ? g_w : g_p);
    dst[4*i + 0] = __halves2half2(__float2half_rn(a.x), __float2half_rn(a.y));
    dst[4*i + 1] = __halves2half2(__float2half_rn(a.z), __float2half_rn(a.w));
    dst[4*i + 2] = __halves2half2(__float2half_rn(b.x), __float2half_rn(b.y));
    dst[4*i + 3] = __halves2half2(__float2half_rn(b.z), __float2half_rn(b.w));
}

// ---------------- HMMA fp16 x2 GEMM --------------------------------------------
// C[M,N] = (Ah+Al)[M,512] @ B[N,512]^T + bias[N];  B single fp16
// MODE 1: A=g_xh/g_xl, B=g_w (N=1536), scatter q/k/v fp16 hi/lo
// MODE 0: A=g_oh/g_ol, B=g_p (N=512), plain fp32 write
#define KCH     32
#define NCHUNK  (DIMC / KCH)        // 16
#define TILE_B  8192                // 128 rows x 64B
#define BUF_B   (3 * TILE_B)        // Ah, Al, B
#define SMEM_GEMM (2 * BUF_B)       // 48 KB

template<int MODE>
__global__ __launch_bounds__(256)
void gemm_mma(const float* __restrict__ bias, float* __restrict__ C) {
    extern __shared__ char smem[];
    const int tid  = threadIdx.x;
    const int lane = tid & 31;
    const int wid  = tid >> 5;
    const int wm   = wid >> 2;
    const int wn   = wid & 3;
    const int m0 = blockIdx.y * 128;
    const int n0 = blockIdx.x * 128;

    const __half* Ah = (MODE == 1) ? g_xh : g_oh;
    const __half* Al = (MODE == 1) ? g_xl : g_ol;
    const __half* Bw = (MODE == 1) ? g_w  : g_p;

    const uint32_t sb = smem_u32(smem);

    const int frow = tid >> 2;
    const int fq   = tid & 3;
    const uint32_t so0 = sw_off(frow,      fq);
    const uint32_t so1 = sw_off(frow + 64, fq);

    float acc[4][4][4];
    #pragma unroll
    for (int i = 0; i < 4; i++)
        #pragma unroll
        for (int j = 0; j < 4; j++)
            #pragma unroll
            for (int k = 0; k < 4; k++) acc[i][j][k] = 0.f;

    #define GLD(P, R, K0) (*(const uint4*)((P) + (size_t)(R)*DIMC + (K0) + fq*8))
    {
        char* bp = smem;
        uint4 p0 = GLD(Ah, m0+frow, 0), p1 = GLD(Ah, m0+frow+64, 0);
        uint4 p2 = GLD(Al, m0+frow, 0), p3 = GLD(Al, m0+frow+64, 0);
        uint4 p4 = GLD(Bw, n0+frow, 0), p5 = GLD(Bw, n0+frow+64, 0);
        *(uint4*)(bp + 0*TILE_B + so0) = p0; *(uint4*)(bp + 0*TILE_B + so1) = p1;
        *(uint4*)(bp + 1*TILE_B + so0) = p2; *(uint4*)(bp + 1*TILE_B + so1) = p3;
        *(uint4*)(bp + 2*TILE_B + so0) = p4; *(uint4*)(bp + 2*TILE_B + so1) = p5;
    }
    __syncthreads();

    const int lr  = lane & 15;
    const int lq2 = lane >> 4;

    for (int c = 0; c < NCHUNK; c++) {
        uint4 p0, p1, p2, p3, p4, p5;
        if (c + 1 < NCHUNK) {
            const int k0 = (c + 1) * KCH;
            p0 = GLD(Ah, m0+frow, k0); p1 = GLD(Ah, m0+frow+64, k0);
            p2 = GLD(Al, m0+frow, k0); p3 = GLD(Al, m0+frow+64, k0);
            p4 = GLD(Bw, n0+frow, k0); p5 = GLD(Bw, n0+frow+64, k0);
        }
        {
            const uint32_t tba = sb + (uint32_t)(c & 1) * BUF_B;
            #pragma unroll
            for (int ks = 0; ks < 2; ks++) {
                uint32_t ah[4][4], al[4][4], bf[4][2];
                #pragma unroll
                for (int mt = 0; mt < 4; mt++) {
                    int r = wm*64 + mt*16 + lr;
                    uint32_t off = sw_off(r, 2*ks + lq2);
                    ldsm_x4(ah[mt][0], ah[mt][1], ah[mt][2], ah[mt][3], tba + off);
                    ldsm_x4(al[mt][0], al[mt][1], al[mt][2], al[mt][3], tba + TILE_B + off);
                }
                #pragma unroll
                for (int g2 = 0; g2 < 2; g2++) {
                    int r = wn*32 + g2*16 + lr;
                    uint32_t off = sw_off(r, 2*ks + lq2);
                    uint32_t t0, t1, t2, t3;
                    ldsm_x4(t0, t1, t2, t3, tba + 2*TILE_B + off);
                    bf[2*g2][0] = t0; bf[2*g2][1] = t2;
                    bf[2*g2+1][0] = t1; bf[2*g2+1][1] = t3;
                }
                #pragma unroll
                for (int mt = 0; mt < 4; mt++)
                    #pragma unroll
                    for (int nt = 0; nt < 4; nt++) {
                        mma_f16(acc[mt][nt], ah[mt], bf[nt]);
                        mma_f16(acc[mt][nt], al[mt], bf[nt]);
                    }
            }
        }
        __syncthreads();
        if (c + 1 < NCHUNK) {
            char* bp = smem + ((c + 1) & 1) * BUF_B;
            *(uint4*)(bp + 0*TILE_B + so0) = p0; *(uint4*)(bp + 0*TILE_B + so1) = p1;
            *(uint4*)(bp + 1*TILE_B + so0) = p2; *(uint4*)(bp + 1*TILE_B + so1) = p3;
            *(uint4*)(bp + 2*TILE_B + so0) = p4; *(uint4*)(bp + 2*TILE_B + so1) = p5;
            __syncthreads();
        }
    }
    #undef GLD

    #pragma unroll
    for (int mt = 0; mt < 4; mt++) {
        #pragma unroll
        for (int nt = 0; nt < 4; nt++) {
            const int col = n0 + wn*32 + nt*8 + (lane & 3)*2;
            const float b0 = bias[col], b1 = bias[col + 1];
            #pragma unroll
            for (int half = 0; half < 2; half++) {
                const int row = m0 + wm*64 + mt*16 + (lane >> 2) + half*8;
                float vx = acc[mt][nt][2*half + 0] + b0;
                float vy = acc[mt][nt][2*half + 1] + b1;
                if (MODE == 0) {
                    *(float2*)(C + (size_t)row*DIMC + col) = make_float2(vx, vy);
                } else {
                    const int which = col >> 9;          // 0=q 1=k 2=v
                    const int head  = (col & 511) >> 5;
                    const int d     = col & 31;
                    __half *dh, *dl;
                    if (which == 0)      { dh = g_qh; dl = g_ql; vx *= QK_SCALE; vy *= QK_SCALE; }
                    else if (which == 1) { dh = g_kh; dl = g_kl; }
                    else                 { dh = g_vh; dl = g_vl; }
                    const int b = row / NT;
                    const int n = row - b*NT;
                    const size_t o = ((size_t)((b*NH + head)*NT + n))*HD + d;
                    __half h0 = __float2half_rn(vx);
                    __half h1 = __float2half_rn(vy);
                    __half l0 = __float2half_rn(vx - __half2float(h0));
                    __half l1 = __float2half_rn(vy - __half2float(h1));
                    *(__half2*)(dh + o) = __halves2half2(h0, h1);
                    *(__half2*)(dl + o) = __halves2half2(l0, l1);
                }
            }
        }
    }
}

// ---------------- HMMA attention: one block per (b,h), register softmax --------
#define AP      112
#define PPITCH  136                 // P fp16 pitch (elems); 272B rows

#define AT_QH 0
#define AT_QL (AT_QH + AP*64)
#define AT_KH (AT_QL + AP*64)
#define AT_KL (AT_KH + AP*64)
#define AT_VH (AT_KL + AP*64)
#define AT_VL (AT_VH + AP*64)
#define AT_PH (AT_VL + AP*64)
#define AT_PL (AT_PH + AP*PPITCH*2)
#define AT_BYTES (AT_PL + AP*PPITCH*2)   // 103936

__global__ __launch_bounds__(256, 2)
void attn_mma_kernel(const float* __restrict__ mask) {
    extern __shared__ char sm[];
    const int tid  = threadIdx.x;
    const int lane = tid & 31;
    const int wid  = tid >> 5;
    const int bh = blockIdx.x;
    const int b  = bh >> 4;
    const int h  = bh & 15;
    const int w  = b & (NWIN - 1);
    const uint32_t sb = smem_u32(sm);

    // ---- fill q/k/v hi/lo tiles (zero pad rows 98..111)
    {
        const __half* gsrc[6] = { g_qh, g_ql, g_kh, g_kl, g_vh, g_vl };
        const size_t gbase = (size_t)bh * (NT*HD);
        for (int c = tid; c < 6*AP*4; c += 256) {
            int mat = c / (AP*4);
            int rem = c % (AP*4);
            int row = rem >> 2, q = rem & 3;
            uint4 val = make_uint4(0, 0, 0, 0);
            if (row < NT)
                val = *(const uint4*)(gsrc[mat] + gbase + (size_t)row*HD + q*8);
            *(uint4*)(sm + mat*AP*64 + sw_off(row, q)) = val;
        }
        // zero P pad rows (both planes)
        for (int c = tid; c < 2*14*68; c += 256) {
            int plane = c / (14*68);
            int rem   = c % (14*68);
            int row   = NT + rem / 68;
            int wd    = rem % 68;
            *(uint32_t*)(sm + (plane ? AT_PL : AT_PH) + row*(PPITCH*2) + wd*4) = 0;
        }
    }
    __syncthreads();

    const int lr  = lane & 15;
    const int lq2 = lane >> 4;

    // ---- S = Q K^T in registers (warp wid owns rows 16*wid..16*wid+15)
    if (wid < 7) {
        uint32_t qh[2][4], ql[2][4];
        #pragma unroll
        for (int ks = 0; ks < 2; ks++) {
            uint32_t off = sw_off(wid*16 + lr, 2*ks + lq2);
            ldsm_x4(qh[ks][0], qh[ks][1], qh[ks][2], qh[ks][3], sb + AT_QH + off);
            ldsm_x4(ql[ks][0], ql[ks][1], ql[ks][2], ql[ks][3], sb + AT_QL + off);
        }
        float c[7][2][4];
        #pragma unroll
        for (int nt = 0; nt < 7; nt++)
            #pragma unroll
            for (int n8 = 0; n8 < 2; n8++)
                #pragma unroll
                for (int e = 0; e < 4; e++) c[nt][n8][e] = 0.f;

        #pragma unroll
        for (int nt = 0; nt < 7; nt++) {
            #pragma unroll
            for (int ks = 0; ks < 2; ks++) {
                uint32_t t0, t1, t2, t3, u0, u1, u2, u3;
                uint32_t off = sw_off(nt*16 + lr, 2*ks + lq2);
                ldsm_x4(t0, t1, t2, t3, sb + AT_KH + off);
                ldsm_x4(u0, u1, u2, u3, sb + AT_KL + off);
                uint32_t kh0[2] = {t0, t2}, kh1[2] = {t1, t3};
                uint32_t kl0[2] = {u0, u2}, kl1[2] = {u1, u3};
                mma_f16(c[nt][0], qh[ks], kh0);
                mma_f16(c[nt][0], qh[ks], kl0);
                mma_f16(c[nt][0], ql[ks], kh0);
                mma_f16(c[nt][1], qh[ks], kh1);
                mma_f16(c[nt][1], qh[ks], kl1);
                mma_f16(c[nt][1], ql[ks], kh1);
            }
        }

        // ---- fused bias+mask, register softmax
        const int i0 = wid*16 + (lane >> 2);
        const int i1 = i0 + 8;
        const float* bi = g_bias + (size_t)h * (NT*NT);
        const float* mk = mask   + (size_t)w * (NT*NT);
        #pragma unroll
        for (int nt = 0; nt < 7; nt++)
            #pragma unroll
            for (int n8 = 0; n8 < 2; n8++) {
                int col = nt*16 + n8*8 + (lane & 3)*2;
                if (col < NT && i0 < NT) {
                    float2 bv = *(const float2*)(bi + (size_t)i0*NT + col);
                    float2 mv = *(const float2*)(mk + (size_t)i0*NT + col);
                    c[nt][n8][0] += bv.x + mv.x;
                    c[nt][n8][1] += bv.y + mv.y;
                } else { c[nt][n8][0] = -1e30f; c[nt][n8][1] = -1e30f; }
                if (col < NT && i1 < NT) {
                    float2 bv = *(const float2*)(bi + (size_t)i1*NT + col);
                    float2 mv = *(const float2*)(mk + (size_t)i1*NT + col);
                    c[nt][n8][2] += bv.x + mv.x;
                    c[nt][n8][3] += bv.y + mv.y;
                } else { c[nt][n8][2] = -1e30f; c[nt][n8][3] = -1e30f; }
            }

        float mx0 = -1e30f, mx1 = -1e30f;
        #pragma unroll
        for (int nt = 0; nt < 7; nt++)
            #pragma unroll
            for (int n8 = 0; n8 < 2; n8++) {
                mx0 = fmaxf(mx0, fmaxf(c[nt][n8][0], c[nt][n8][1]));
                mx1 = fmaxf(mx1, fmaxf(c[nt][n8][2], c[nt][n8][3]));
            }
        #pragma unroll
        for (int off = 1; off <= 2; off <<= 1) {
            mx0 = fmaxf(mx0, __shfl_xor_sync(0xffffffffu, mx0, off));
            mx1 = fmaxf(mx1, __shfl_xor_sync(0xffffffffu, mx1, off));
        }
        float s0 = 0.f, s1 = 0.f;
        #pragma unroll
        for (int nt = 0; nt < 7; nt++)
            #pragma unroll
            for (int n8 = 0; n8 < 2; n8++) {
                float e0 = __expf(c[nt][n8][0] - mx0);
                float e1 = __expf(c[nt][n8][1] - mx0);
                float e2 = __expf(c[nt][n8][2] - mx1);
                float e3 = __expf(c[nt][n8][3] - mx1);
                c[nt][n8][0] = e0; c[nt][n8][1] = e1;
                c[nt][n8][2] = e2; c[nt][n8][3] = e3;
                s0 += e0 + e1; s1 += e2 + e3;
            }
        #pragma unroll
        for (int off = 1; off <= 2; off <<= 1) {
            s0 += __shfl_xor_sync(0xffffffffu, s0, off);
            s1 += __shfl_xor_sync(0xffffffffu, s1, off);
        }
        const float r0 = 1.f / s0, r1 = 1.f / s1;

        __half* Ph = (__half*)(sm + AT_PH);
        __half* Pl = (__half*)(sm + AT_PL);
        #pragma unroll
        for (int nt = 0; nt < 7; nt++)
            #pragma unroll
            for (int n8 = 0; n8 < 2; n8++) {
                int col = nt*16 + n8*8 + (lane & 3)*2;
                float p0 = c[nt][n8][0] * r0, p1 = c[nt][n8][1] * r0;
                float p2 = c[nt][n8][2] * r1, p3 = c[nt][n8][3] * r1;
                __half a0 = __float2half_rn(p0), a1 = __float2half_rn(p1);
                __half a2 = __float2half_rn(p2), a3 = __float2half_rn(p3);
                __half b0 = __float2half_rn(p0 - __half2float(a0));
                __half b1 = __float2half_rn(p1 - __half2float(a1));
                __half b2 = __float2half_rn(p2 - __half2float(a2));
                __half b3 = __float2half_rn(p3 - __half2float(a3));
                *(__half2*)(Ph + (size_t)i0*PPITCH + col) = __halves2half2(a0, a1);
                *(__half2*)(Ph + (size_t)i1*PPITCH + col) = __halves2half2(a2, a3);
                *(__half2*)(Pl + (size_t)i0*PPITCH + col) = __halves2half2(b0, b1);
                *(__half2*)(Pl + (size_t)i1*PPITCH + col) = __halves2half2(b2, b3);
            }
    }
    __syncthreads();

    // ---- out = P V (fp16 hi/lo x3), write g_oh/g_ol
    for (int pos = wid; pos < 14; pos += 8) {
        int mt = pos >> 1, nt = pos & 1;
        float cc[2][4] = {};
        for (int kt = 0; kt < 7; kt++) {
            uint32_t pa[4], pb[4];
            uint32_t offp = (uint32_t)(mt*16 + lr)*(PPITCH*2) + (uint32_t)(kt*2 + lq2)*16;
            ldsm_x4(pa[0], pa[1], pa[2], pa[3], sb + AT_PH + offp);
            ldsm_x4(pb[0], pb[1], pb[2], pb[3], sb + AT_PL + offp);
            uint32_t offv = sw_off(kt*16 + lr, nt*2 + lq2);
            uint32_t t0, t1, t2, t3;
            ldsm_x4_t(t0, t1, t2, t3, sb + AT_VH + offv);
            uint32_t vh0[2] = {t0, t1}, vh1[2] = {t2, t3};
            ldsm_x4_t(t0, t1, t2, t3, sb + AT_VL + offv);
            uint32_t vl0[2] = {t0, t1}, vl1[2] = {t2, t3};
            mma_f16(cc[0], pa, vh0);
            mma_f16(cc[0], pa, vl0);
            mma_f16(cc[0], pb, vh0);
            mma_f16(cc[1], pa, vh1);
            mma_f16(cc[1], pa, vl1);
            mma_f16(cc[1], pb, vh1);
        }
        #pragma unroll
        for (int n8 = 0; n8 < 2; n8++)
            #pragma unroll
            for (int half = 0; half < 2; half++) {
                int i = mt*16 + (lane >> 2) + half*8;
                if (i < NT) {
                    int d = nt*16 + n8*8 + (lane & 3)*2;
                    float v0 = cc[n8][2*half], v1 = cc[n8][2*half + 1];
                    __half h0 = __float2half_rn(v0);
                    __half h1 = __float2half_rn(v1);
                    __half l0 = __float2half_rn(v0 - __half2float(h0));
                    __half l1 = __float2half_rn(v1 - __half2float(h1));
                    size_t o = (size_t)(b*NT + i)*DIMC + h*HD + d;
                    *(__half2*)(g_oh + o) = __halves2half2(h0, h1);
                    *(__half2*)(g_ol + o) = __halves2half2(l0, l1);
                }
            }
    }
}

// ---------------- launch --------------------------------------------------------
extern "C" void kernel_launch(void* const* d_in, const int* in_sizes, int n_in,
                              void* d_out, int out_size) {
    const float* x          = (const float*)d_in[0];
    const float* mask       = (const float*)d_in[1];
    const float* qkv_w      = (const float*)d_in[2];
    const float* qkv_b      = (const float*)d_in[3];
    const float* proj_w     = (const float*)d_in[4];
    const float* proj_b     = (const float*)d_in[5];
    const float* bias_table = (const float*)d_in[6];
    const int*   rel_index  = (const int*)  d_in[7];
    float* out = (float*)d_out;

    cudaFuncSetAttribute(attn_mma_kernel,
                         cudaFuncAttributeMaxDynamicSharedMemorySize, AT_BYTES);
    cudaFuncSetAttribute(gemm_mma<0>,
                         cudaFuncAttributeMaxDynamicSharedMemorySize, SMEM_GEMM);
    cudaFuncSetAttribute(gemm_mma<1>,
                         cudaFuncAttributeMaxDynamicSharedMemorySize, SMEM_GEMM);

    bias_gather_kernel<<<(NH*NT*NT + 255)/256, 256>>>(bias_table, rel_index);
    split_x_kernel<<<(MROWS*DIMC/8 + 255)/256, 256>>>(x, MROWS*DIMC/8);
    cvt_kernel<0><<<(3*DIMC*DIMC/8 + 255)/256, 256>>>(qkv_w, 3*DIMC*DIMC/8);
    cvt_kernel<1><<<(DIMC*DIMC/8 + 255)/256, 256>>>(proj_w, DIMC*DIMC/8);

    gemm_mma<1><<<dim3(3*DIMC/128, MROWS/128), 256, SMEM_GEMM>>>(qkv_b, nullptr);
    attn_mma_kernel<<<NB*NH, 256, AT_BYTES>>>(mask);
    gemm_mma<0><<<dim3(DIMC/128, MROWS/128), 256, SMEM_GEMM>>>(proj_b, out);
}

// round 10
// speedup vs baseline: 3.8829x; 1.3493x over previous
#include <cuda_runtime.h>
#include <cuda_fp16.h>
#include <math.h>
#include <stdint.h>

#define NB    512
#define NT    98
#define DIMC  512
#define NH    16
#define HD    32
#define NWIN  64
#define MROWS (NB*NT)                 // 50176
#define QK_SCALE 0.17677669529663687f

// ---------------- scratch (device globals; no runtime alloc) ---------------
__device__ __align__(16) __half g_x [(size_t)MROWS*DIMC];    // x fp16
__device__ __align__(16) __half g_w [(size_t)3*DIMC*DIMC];   // qkv_w fp16
__device__ __align__(16) __half g_p [(size_t)DIMC*DIMC];     // proj_w fp16
__device__ __align__(16) __half g_o [(size_t)MROWS*DIMC];    // attn out fp16

// q/k/v hi/lo fp16, layout [(b*NH+h)*NT + n][HD]
__device__ __align__(16) __half g_qh[(size_t)NB*NH*NT*HD];
__device__ __align__(16) __half g_ql[(size_t)NB*NH*NT*HD];
__device__ __align__(16) __half g_kh[(size_t)NB*NH*NT*HD];
__device__ __align__(16) __half g_kl[(size_t)NB*NH*NT*HD];
__device__ __align__(16) __half g_vh[(size_t)NB*NH*NT*HD];
__device__ __align__(16) __half g_vl[(size_t)NB*NH*NT*HD];

__device__ float g_bias[NH*NT*NT];

// ---------------- helpers ----------------------------------------------------
__device__ __forceinline__ uint32_t smem_u32(const void* p) {
    uint32_t a;
    asm("{ .reg .u64 t; cvta.to.shared.u64 t, %1; cvt.u32.u64 %0, t; }"
        : "=r"(a) : "l"(p));
    return a;
}
__device__ __forceinline__ void ldsm_x4(uint32_t& r0, uint32_t& r1,
                                        uint32_t& r2, uint32_t& r3, uint32_t addr) {
    asm volatile("ldmatrix.sync.aligned.m8n8.x4.shared.b16 {%0,%1,%2,%3}, [%4];"
                 : "=r"(r0), "=r"(r1), "=r"(r2), "=r"(r3) : "r"(addr));
}
__device__ __forceinline__ void ldsm_x4_t(uint32_t& r0, uint32_t& r1,
                                          uint32_t& r2, uint32_t& r3, uint32_t addr) {
    asm volatile("ldmatrix.sync.aligned.m8n8.x4.trans.shared.b16 {%0,%1,%2,%3}, [%4];"
                 : "=r"(r0), "=r"(r1), "=r"(r2), "=r"(r3) : "r"(addr));
}
__device__ __forceinline__ void mma_f16(float* c, const uint32_t* a, const uint32_t* b) {
    asm volatile(
        "mma.sync.aligned.m16n8k16.row.col.f32.f16.f16.f32 "
        "{%0,%1,%2,%3}, {%4,%5,%6,%7}, {%8,%9}, {%0,%1,%2,%3};"
        : "+f"(c[0]), "+f"(c[1]), "+f"(c[2]), "+f"(c[3])
        : "r"(a[0]), "r"(a[1]), "r"(a[2]), "r"(a[3]), "r"(b[0]), "r"(b[1]));
}
__device__ __forceinline__ void cpa16(uint32_t saddr, const void* g) {
    asm volatile("cp.async.cg.shared.global [%0], [%1], 16;"
                 :: "r"(saddr), "l"(g) : "memory");
}
// byte offset in a [rows]x32-fp16 tile (64B rows) for (row, 16B-quarter q)
__device__ __forceinline__ uint32_t sw_off(int row, int q) {
    return (uint32_t)(row * 64 + ((q ^ ((row >> 1) & 3)) << 4));
}

// ---------------- bias gather ------------------------------------------------
__global__ void bias_gather_kernel(const float* __restrict__ bt,
                                   const int* __restrict__ ri) {
    int idx = blockIdx.x * blockDim.x + threadIdx.x;
    if (idx < NH*NT*NT) {
        int h  = idx / (NT*NT);
        int ij = idx - h*(NT*NT);
        g_bias[idx] = bt[ri[ij]*NH + h];
    }
}

// ---------------- fp32 -> fp16 convert ----------------------------------------
template<int DST>   // 0 -> g_w, 1 -> g_p, 2 -> g_x
__global__ void cvt_kernel(const float* __restrict__ src, int n8) {
    int i = blockIdx.x * blockDim.x + threadIdx.x;
    if (i >= n8) return;
    float4 a = ((const float4*)src)[2*i];
    float4 b = ((const float4*)src)[2*i + 1];
    __half2* dst = (__half2*)((DST == 0) ? g_w : (DST == 1) ? g_p : g_x);
    dst[4*i + 0] = __halves2half2(__float2half_rn(a.x), __float2half_rn(a.y));
    dst[4*i + 1] = __halves2half2(__float2half_rn(a.z), __float2half_rn(a.w));
    dst[4*i + 2] = __halves2half2(__float2half_rn(b.x), __float2half_rn(b.y));
    dst[4*i + 3] = __halves2half2(__float2half_rn(b.z), __float2half_rn(b.w));
}

// ---------------- HMMA fp16 GEMM (cp.async 4-stage pipeline) -------------------
// C[M,N] = A[M,512] @ B[N,512]^T + bias[N]
// MODE 1: A=g_x, B=g_w (N=1536), scatter q/k/v fp16 hi/lo
// MODE 0: A=g_o, B=g_p (N=512), fp32 write to d_out
#define KCH      32
#define NCHUNK   (DIMC / KCH)        // 16
#define TILE_B2  8192                // 128 rows x 64B
#define STAGE_B  (2 * TILE_B2)       // A + B
#define NSTAGE   4
#define SMEM_GEMM (NSTAGE * STAGE_B) // 64 KB

template<int MODE>
__global__ __launch_bounds__(256)
void gemm_mma(const float* __restrict__ bias, float* __restrict__ C) {
    extern __shared__ char smem[];
    const int tid  = threadIdx.x;
    const int lane = tid & 31;
    const int wid  = tid >> 5;
    const int wm   = wid >> 2;
    const int wn   = wid & 3;
    const int m0 = blockIdx.y * 128;
    const int n0 = blockIdx.x * 128;

    const __half* A = (MODE == 1) ? g_x : g_o;
    const __half* B = (MODE == 1) ? g_w : g_p;

    const uint32_t sb = smem_u32(smem);
    const int frow = tid >> 1;
    const int fq0  = (tid & 1) * 2;

    float acc[4][4][4];
    #pragma unroll
    for (int i = 0; i < 4; i++)
        #pragma unroll
        for (int j = 0; j < 4; j++)
            #pragma unroll
            for (int k = 0; k < 4; k++) acc[i][j][k] = 0.f;

    // prologue: stages 0..2
    #pragma unroll
    for (int s = 0; s < NSTAGE - 1; s++) {
        const int k0 = s * KCH;
        const uint32_t base = sb + s * STAGE_B;
        cpa16(base + sw_off(frow, fq0),
              A + (size_t)(m0 + frow)*DIMC + k0 + fq0*8);
        cpa16(base + sw_off(frow, fq0 + 1),
              A + (size_t)(m0 + frow)*DIMC + k0 + fq0*8 + 8);
        cpa16(base + TILE_B2 + sw_off(frow, fq0),
              B + (size_t)(n0 + frow)*DIMC + k0 + fq0*8);
        cpa16(base + TILE_B2 + sw_off(frow, fq0 + 1),
              B + (size_t)(n0 + frow)*DIMC + k0 + fq0*8 + 8);
        asm volatile("cp.async.commit_group;" ::: "memory");
    }

    const int lr  = lane & 15;
    const int lq2 = lane >> 4;

    for (int c = 0; c < NCHUNK; c++) {
        asm volatile("cp.async.wait_group 2;" ::: "memory");
        __syncthreads();

        const uint32_t tba = sb + (uint32_t)(c & 3) * STAGE_B;
        #pragma unroll
        for (int ks = 0; ks < 2; ks++) {
            uint32_t af[4][4], bf[4][2];
            #pragma unroll
            for (int mt = 0; mt < 4; mt++) {
                uint32_t off = sw_off(wm*64 + mt*16 + lr, 2*ks + lq2);
                ldsm_x4(af[mt][0], af[mt][1], af[mt][2], af[mt][3], tba + off);
            }
            #pragma unroll
            for (int g2 = 0; g2 < 2; g2++) {
                uint32_t off = sw_off(wn*32 + g2*16 + lr, 2*ks + lq2);
                uint32_t t0, t1, t2, t3;
                ldsm_x4(t0, t1, t2, t3, tba + TILE_B2 + off);
                bf[2*g2][0] = t0; bf[2*g2][1] = t2;
                bf[2*g2+1][0] = t1; bf[2*g2+1][1] = t3;
            }
            #pragma unroll
            for (int mt = 0; mt < 4; mt++)
                #pragma unroll
                for (int nt = 0; nt < 4; nt++)
                    mma_f16(acc[mt][nt], af[mt], bf[nt]);
        }

        if (c + NSTAGE - 1 < NCHUNK) {
            const int s  = (c + NSTAGE - 1) & 3;
            const int k0 = (c + NSTAGE - 1) * KCH;
            const uint32_t base = sb + s * STAGE_B;
            cpa16(base + sw_off(frow, fq0),
                  A + (size_t)(m0 + frow)*DIMC + k0 + fq0*8);
            cpa16(base + sw_off(frow, fq0 + 1),
                  A + (size_t)(m0 + frow)*DIMC + k0 + fq0*8 + 8);
            cpa16(base + TILE_B2 + sw_off(frow, fq0),
                  B + (size_t)(n0 + frow)*DIMC + k0 + fq0*8);
            cpa16(base + TILE_B2 + sw_off(frow, fq0 + 1),
                  B + (size_t)(n0 + frow)*DIMC + k0 + fq0*8 + 8);
        }
        asm volatile("cp.async.commit_group;" ::: "memory");
    }

    // ---- epilogue
    #pragma unroll
    for (int mt = 0; mt < 4; mt++) {
        #pragma unroll
        for (int nt = 0; nt < 4; nt++) {
            const int col = n0 + wn*32 + nt*8 + (lane & 3)*2;
            const float b0 = bias[col], b1 = bias[col + 1];
            #pragma unroll
            for (int half = 0; half < 2; half++) {
                const int row = m0 + wm*64 + mt*16 + (lane >> 2) + half*8;
                float vx = acc[mt][nt][2*half + 0] + b0;
                float vy = acc[mt][nt][2*half + 1] + b1;
                if (MODE == 0) {
                    *(float2*)(C + (size_t)row*DIMC + col) = make_float2(vx, vy);
                } else {
                    const int which = col >> 9;          // 0=q 1=k 2=v
                    const int head  = (col & 511) >> 5;
                    const int d     = col & 31;
                    __half *dh, *dl;
                    if (which == 0)      { dh = g_qh; dl = g_ql; vx *= QK_SCALE; vy *= QK_SCALE; }
                    else if (which == 1) { dh = g_kh; dl = g_kl; }
                    else                 { dh = g_vh; dl = g_vl; }
                    const int b = row / NT;
                    const int n = row - b*NT;
                    const size_t o = ((size_t)((b*NH + head)*NT + n))*HD + d;
                    __half h0 = __float2half_rn(vx);
                    __half h1 = __float2half_rn(vy);
                    __half l0 = __float2half_rn(vx - __half2float(h0));
                    __half l1 = __float2half_rn(vy - __half2float(h1));
                    *(__half2*)(dh + o) = __halves2half2(h0, h1);
                    *(__half2*)(dl + o) = __halves2half2(l0, l1);
                }
            }
        }
    }
}

// ---------------- HMMA attention: one block per (b,h), register softmax --------
#define AP      112
#define PPITCH  136                 // P fp16 pitch (elems); 272B rows

#define AT_QH 0
#define AT_QL (AT_QH + AP*64)
#define AT_KH (AT_QL + AP*64)
#define AT_KL (AT_KH + AP*64)
#define AT_VH (AT_KL + AP*64)
#define AT_VL (AT_VH + AP*64)
#define AT_PH (AT_VL + AP*64)
#define AT_PL (AT_PH + AP*PPITCH*2)
#define AT_BYTES (AT_PL + AP*PPITCH*2)   // 103936

__global__ __launch_bounds__(256, 2)
void attn_mma_kernel(const float* __restrict__ mask) {
    extern __shared__ char sm[];
    const int tid  = threadIdx.x;
    const int lane = tid & 31;
    const int wid  = tid >> 5;
    const int bh = blockIdx.x;
    const int b  = bh >> 4;
    const int h  = bh & 15;
    const int w  = b & (NWIN - 1);
    const uint32_t sb = smem_u32(sm);

    // ---- fill q/k/v hi/lo tiles (zero pad rows 98..111)
    {
        const __half* gsrc[6] = { g_qh, g_ql, g_kh, g_kl, g_vh, g_vl };
        const size_t gbase = (size_t)bh * (NT*HD);
        for (int c = tid; c < 6*AP*4; c += 256) {
            int mat = c / (AP*4);
            int rem = c % (AP*4);
            int row = rem >> 2, q = rem & 3;
            uint4 val = make_uint4(0, 0, 0, 0);
            if (row < NT)
                val = *(const uint4*)(gsrc[mat] + gbase + (size_t)row*HD + q*8);
            *(uint4*)(sm + mat*AP*64 + sw_off(row, q)) = val;
        }
        // zero P pad rows (both planes)
        for (int c = tid; c < 2*14*68; c += 256) {
            int plane = c / (14*68);
            int rem   = c % (14*68);
            int row   = NT + rem / 68;
            int wd    = rem % 68;
            *(uint32_t*)(sm + (plane ? AT_PL : AT_PH) + row*(PPITCH*2) + wd*4) = 0;
        }
    }
    __syncthreads();

    const int lr  = lane & 15;
    const int lq2 = lane >> 4;

    // ---- S = Q K^T in registers (warp wid owns rows 16*wid..16*wid+15)
    if (wid < 7) {
        uint32_t qh[2][4], ql[2][4];
        #pragma unroll
        for (int ks = 0; ks < 2; ks++) {
            uint32_t off = sw_off(wid*16 + lr, 2*ks + lq2);
            ldsm_x4(qh[ks][0], qh[ks][1], qh[ks][2], qh[ks][3], sb + AT_QH + off);
            ldsm_x4(ql[ks][0], ql[ks][1], ql[ks][2], ql[ks][3], sb + AT_QL + off);
        }
        float c[7][2][4];
        #pragma unroll
        for (int nt = 0; nt < 7; nt++)
            #pragma unroll
            for (int n8 = 0; n8 < 2; n8++)
                #pragma unroll
                for (int e = 0; e < 4; e++) c[nt][n8][e] = 0.f;

        #pragma unroll
        for (int nt = 0; nt < 7; nt++) {
            #pragma unroll
            for (int ks = 0; ks < 2; ks++) {
                uint32_t t0, t1, t2, t3, u0, u1, u2, u3;
                uint32_t off = sw_off(nt*16 + lr, 2*ks + lq2);
                ldsm_x4(t0, t1, t2, t3, sb + AT_KH + off);
                ldsm_x4(u0, u1, u2, u3, sb + AT_KL + off);
                uint32_t kh0[2] = {t0, t2}, kh1[2] = {t1, t3};
                uint32_t kl0[2] = {u0, u2}, kl1[2] = {u1, u3};
                mma_f16(c[nt][0], qh[ks], kh0);
                mma_f16(c[nt][0], qh[ks], kl0);
                mma_f16(c[nt][0], ql[ks], kh0);
                mma_f16(c[nt][1], qh[ks], kh1);
                mma_f16(c[nt][1], qh[ks], kl1);
                mma_f16(c[nt][1], ql[ks], kh1);
            }
        }

        // ---- fused bias+mask, register softmax
        const int i0 = wid*16 + (lane >> 2);
        const int i1 = i0 + 8;
        const float* bi = g_bias + (size_t)h * (NT*NT);
        const float* mk = mask   + (size_t)w * (NT*NT);
        #pragma unroll
        for (int nt = 0; nt < 7; nt++)
            #pragma unroll
            for (int n8 = 0; n8 < 2; n8++) {
                int col = nt*16 + n8*8 + (lane & 3)*2;
                if (col < NT && i0 < NT) {
                    float2 bv = *(const float2*)(bi + (size_t)i0*NT + col);
                    float2 mv = *(const float2*)(mk + (size_t)i0*NT + col);
                    c[nt][n8][0] += bv.x + mv.x;
                    c[nt][n8][1] += bv.y + mv.y;
                } else { c[nt][n8][0] = -1e30f; c[nt][n8][1] = -1e30f; }
                if (col < NT && i1 < NT) {
                    float2 bv = *(const float2*)(bi + (size_t)i1*NT + col);
                    float2 mv = *(const float2*)(mk + (size_t)i1*NT + col);
                    c[nt][n8][2] += bv.x + mv.x;
                    c[nt][n8][3] += bv.y + mv.y;
                } else { c[nt][n8][2] = -1e30f; c[nt][n8][3] = -1e30f; }
            }

        float mx0 = -1e30f, mx1 = -1e30f;
        #pragma unroll
        for (int nt = 0; nt < 7; nt++)
            #pragma unroll
            for (int n8 = 0; n8 < 2; n8++) {
                mx0 = fmaxf(mx0, fmaxf(c[nt][n8][0], c[nt][n8][1]));
                mx1 = fmaxf(mx1, fmaxf(c[nt][n8][2], c[nt][n8][3]));
            }
        #pragma unroll
        for (int off = 1; off <= 2; off <<= 1) {
            mx0 = fmaxf(mx0, __shfl_xor_sync(0xffffffffu, mx0, off));
            mx1 = fmaxf(mx1, __shfl_xor_sync(0xffffffffu, mx1, off));
        }
        float s0 = 0.f, s1 = 0.f;
        #pragma unroll
        for (int nt = 0; nt < 7; nt++)
            #pragma unroll
            for (int n8 = 0; n8 < 2; n8++) {
                float e0 = __expf(c[nt][n8][0] - mx0);
                float e1 = __expf(c[nt][n8][1] - mx0);
                float e2 = __expf(c[nt][n8][2] - mx1);
                float e3 = __expf(c[nt][n8][3] - mx1);
                c[nt][n8][0] = e0; c[nt][n8][1] = e1;
                c[nt][n8][2] = e2; c[nt][n8][3] = e3;
                s0 += e0 + e1; s1 += e2 + e3;
            }
        #pragma unroll
        for (int off = 1; off <= 2; off <<= 1) {
            s0 += __shfl_xor_sync(0xffffffffu, s0, off);
            s1 += __shfl_xor_sync(0xffffffffu, s1, off);
        }
        const float r0 = 1.f / s0, r1 = 1.f / s1;

        __half* Ph = (__half*)(sm + AT_PH);
        __half* Pl = (__half*)(sm + AT_PL);
        #pragma unroll
        for (int nt = 0; nt < 7; nt++)
            #pragma unroll
            for (int n8 = 0; n8 < 2; n8++) {
                int col = nt*16 + n8*8 + (lane & 3)*2;
                float p0 = c[nt][n8][0] * r0, p1 = c[nt][n8][1] * r0;
                float p2 = c[nt][n8][2] * r1, p3 = c[nt][n8][3] * r1;
                __half a0 = __float2half_rn(p0), a1 = __float2half_rn(p1);
                __half a2 = __float2half_rn(p2), a3 = __float2half_rn(p3);
                __half b0 = __float2half_rn(p0 - __half2float(a0));
                __half b1 = __float2half_rn(p1 - __half2float(a1));
                __half b2 = __float2half_rn(p2 - __half2float(a2));
                __half b3 = __float2half_rn(p3 - __half2float(a3));
                *(__half2*)(Ph + (size_t)i0*PPITCH + col) = __halves2half2(a0, a1);
                *(__half2*)(Ph + (size_t)i1*PPITCH + col) = __halves2half2(a2, a3);
                *(__half2*)(Pl + (size_t)i0*PPITCH + col) = __halves2half2(b0, b1);
                *(__half2*)(Pl + (size_t)i1*PPITCH + col) = __halves2half2(b2, b3);
            }
    }
    __syncthreads();

    // ---- out = P V (fp16 hi/lo x3), single fp16 store to g_o
    for (int pos = wid; pos < 14; pos += 8) {
        int mt = pos >> 1, nt = pos & 1;
        float cc[2][4] = {};
        for (int kt = 0; kt < 7; kt++) {
            uint32_t pa[4], pb[4];
            uint32_t offp = (uint32_t)(mt*16 + lr)*(PPITCH*2) + (uint32_t)(kt*2 + lq2)*16;
            ldsm_x4(pa[0], pa[1], pa[2], pa[3], sb + AT_PH + offp);
            ldsm_x4(pb[0], pb[1], pb[2], pb[3], sb + AT_PL + offp);
            uint32_t offv = sw_off(kt*16 + lr, nt*2 + lq2);
            uint32_t t0, t1, t2, t3;
            ldsm_x4_t(t0, t1, t2, t3, sb + AT_VH + offv);
            uint32_t vh0[2] = {t0, t1}, vh1[2] = {t2, t3};
            ldsm_x4_t(t0, t1, t2, t3, sb + AT_VL + offv);
            uint32_t vl0[2] = {t0, t1}, vl1[2] = {t2, t3};
            mma_f16(cc[0], pa, vh0);
            mma_f16(cc[0], pa, vl0);
            mma_f16(cc[0], pb, vh0);
            mma_f16(cc[1], pa, vh1);
            mma_f16(cc[1], pa, vl1);
            mma_f16(cc[1], pb, vh1);
        }
        #pragma unroll
        for (int n8 = 0; n8 < 2; n8++)
            #pragma unroll
            for (int half = 0; half < 2; half++) {
                int i = mt*16 + (lane >> 2) + half*8;
                if (i < NT) {
                    int d = nt*16 + n8*8 + (lane & 3)*2;
                    __half h0 = __float2half_rn(cc[n8][2*half]);
                    __half h1 = __float2half_rn(cc[n8][2*half + 1]);
                    size_t o = (size_t)(b*NT + i)*DIMC + h*HD + d;
                    *(__half2*)(g_o + o) = __halves2half2(h0, h1);
                }
            }
    }
}

// ---------------- launch --------------------------------------------------------
extern "C" void kernel_launch(void* const* d_in, const int* in_sizes, int n_in,
                              void* d_out, int out_size) {
    const float* x          = (const float*)d_in[0];
    const float* mask       = (const float*)d_in[1];
    const float* qkv_w      = (const float*)d_in[2];
    const float* qkv_b      = (const float*)d_in[3];
    const float* proj_w     = (const float*)d_in[4];
    const float* proj_b     = (const float*)d_in[5];
    const float* bias_table = (const float*)d_in[6];
    const int*   rel_index  = (const int*)  d_in[7];
    float* out = (float*)d_out;

    cudaFuncSetAttribute(attn_mma_kernel,
                         cudaFuncAttributeMaxDynamicSharedMemorySize, AT_BYTES);
    cudaFuncSetAttribute(gemm_mma<0>,
                         cudaFuncAttributeMaxDynamicSharedMemorySize, SMEM_GEMM);
    cudaFuncSetAttribute(gemm_mma<1>,
                         cudaFuncAttributeMaxDynamicSharedMemorySize, SMEM_GEMM);

    bias_gather_kernel<<<(NH*NT*NT + 255)/256, 256>>>(bias_table, rel_index);
    cvt_kernel<2><<<(MROWS*DIMC/8 + 255)/256, 256>>>(x, MROWS*DIMC/8);
    cvt_kernel<0><<<(3*DIMC*DIMC/8 + 255)/256, 256>>>(qkv_w, 3*DIMC*DIMC/8);
    cvt_kernel<1><<<(DIMC*DIMC/8 + 255)/256, 256>>>(proj_w, DIMC*DIMC/8);

    gemm_mma<1><<<dim3(3*DIMC/128, MROWS/128), 256, SMEM_GEMM>>>(qkv_b, nullptr);
    attn_mma_kernel<<<NB*NH, 256, AT_BYTES>>>(mask);
    gemm_mma<0><<<dim3(DIMC/128, MROWS/128), 256, SMEM_GEMM>>>(proj_b, out);
}

// round 11
// speedup vs baseline: 4.4517x; 1.1465x over previous
#include <cuda_runtime.h>
#include <cuda_fp16.h>
#include <math.h>
#include <stdint.h>

#define NB    512
#define NT    98
#define DIMC  512
#define NH    16
#define HD    32
#define NWIN  64
#define MROWS (NB*NT)                 // 50176
#define QK_SCALE 0.17677669529663687f

// ---------------- scratch (device globals; no runtime alloc) ---------------
__device__ __align__(16) __half g_x [(size_t)MROWS*DIMC];    // x fp16
__device__ __align__(16) __half g_w [(size_t)3*DIMC*DIMC];   // qkv_w fp16
__device__ __align__(16) __half g_p [(size_t)DIMC*DIMC];     // proj_w fp16
__device__ __align__(16) __half g_o [(size_t)MROWS*DIMC];    // attn out fp16

// q/k hi/lo, v single fp16; layout [(b*NH+h)*NT + n][HD]
__device__ __align__(16) __half g_qh[(size_t)NB*NH*NT*HD];
__device__ __align__(16) __half g_ql[(size_t)NB*NH*NT*HD];
__device__ __align__(16) __half g_kh[(size_t)NB*NH*NT*HD];
__device__ __align__(16) __half g_kl[(size_t)NB*NH*NT*HD];
__device__ __align__(16) __half g_v [(size_t)NB*NH*NT*HD];

__device__ float g_bias[NH*NT*NT];

// ---------------- helpers ----------------------------------------------------
__device__ __forceinline__ uint32_t smem_u32(const void* p) {
    uint32_t a;
    asm("{ .reg .u64 t; cvta.to.shared.u64 t, %1; cvt.u32.u64 %0, t; }"
        : "=r"(a) : "l"(p));
    return a;
}
__device__ __forceinline__ void ldsm_x4(uint32_t& r0, uint32_t& r1,
                                        uint32_t& r2, uint32_t& r3, uint32_t addr) {
    asm volatile("ldmatrix.sync.aligned.m8n8.x4.shared.b16 {%0,%1,%2,%3}, [%4];"
                 : "=r"(r0), "=r"(r1), "=r"(r2), "=r"(r3) : "r"(addr));
}
__device__ __forceinline__ void ldsm_x4_t(uint32_t& r0, uint32_t& r1,
                                          uint32_t& r2, uint32_t& r3, uint32_t addr) {
    asm volatile("ldmatrix.sync.aligned.m8n8.x4.trans.shared.b16 {%0,%1,%2,%3}, [%4];"
                 : "=r"(r0), "=r"(r1), "=r"(r2), "=r"(r3) : "r"(addr));
}
__device__ __forceinline__ void mma_f16(float* c, const uint32_t* a, const uint32_t* b) {
    asm volatile(
        "mma.sync.aligned.m16n8k16.row.col.f32.f16.f16.f32 "
        "{%0,%1,%2,%3}, {%4,%5,%6,%7}, {%8,%9}, {%0,%1,%2,%3};"
        : "+f"(c[0]), "+f"(c[1]), "+f"(c[2]), "+f"(c[3])
        : "r"(a[0]), "r"(a[1]), "r"(a[2]), "r"(a[3]), "r"(b[0]), "r"(b[1]));
}
__device__ __forceinline__ void cpa16(uint32_t saddr, const void* g) {
    asm volatile("cp.async.cg.shared.global [%0], [%1], 16;"
                 :: "r"(saddr), "l"(g) : "memory");
}
// byte offset in a [rows]x32-fp16 tile (64B rows) for (row, 16B-quarter q)
__device__ __forceinline__ uint32_t sw_off(int row, int q) {
    return (uint32_t)(row * 64 + ((q ^ ((row >> 1) & 3)) << 4));
}

// ---------------- fused preprocessing: converts + bias gather -----------------
#define N8X  (MROWS*DIMC/8)          // 3211264 -> 12544 blocks
#define N8W  (3*DIMC*DIMC/8)         // 98304   -> 384 blocks
#define N8P  (DIMC*DIMC/8)           // 32768   -> 128 blocks
#define BX   (N8X/256)
#define BW   (N8W/256)
#define BP   (N8P/256)
#define BBIAS ((NH*NT*NT + 255)/256) // 601
#define PRE_BLOCKS (BX + BW + BP + BBIAS)

__global__ void pre_kernel(const float* __restrict__ x,
                           const float* __restrict__ qkv_w,
                           const float* __restrict__ proj_w,
                           const float* __restrict__ bt,
                           const int*   __restrict__ ri) {
    int blk = blockIdx.x;
    if (blk < BX + BW + BP) {
        const float* src;
        __half2* dst;
        int i;
        if (blk < BX)            { src = x;      dst = (__half2*)g_x; i = blk*256 + threadIdx.x; }
        else if (blk < BX + BW)  { src = qkv_w;  dst = (__half2*)g_w; i = (blk-BX)*256 + threadIdx.x; }
        else                     { src = proj_w; dst = (__half2*)g_p; i = (blk-BX-BW)*256 + threadIdx.x; }
        float4 a = ((const float4*)src)[2*i];
        float4 b = ((const float4*)src)[2*i + 1];
        dst[4*i + 0] = __halves2half2(__float2half_rn(a.x), __float2half_rn(a.y));
        dst[4*i + 1] = __halves2half2(__float2half_rn(a.z), __float2half_rn(a.w));
        dst[4*i + 2] = __halves2half2(__float2half_rn(b.x), __float2half_rn(b.y));
        dst[4*i + 3] = __halves2half2(__float2half_rn(b.z), __float2half_rn(b.w));
    } else {
        int idx = (blk - BX - BW - BP)*256 + threadIdx.x;
        if (idx < NH*NT*NT) {
            int h  = idx / (NT*NT);
            int ij = idx - h*(NT*NT);
            g_bias[idx] = bt[ri[ij]*NH + h];
        }
    }
}

// ---------------- HMMA fp16 GEMM (cp.async 4-stage pipeline) -------------------
// C[M,N] = A[M,512] @ B[N,512]^T + bias[N]
// MODE 1: A=g_x, B=g_w (N=1536), scatter q/k hi/lo + v single
// MODE 0: A=g_o, B=g_p (N=512), fp32 write to d_out
#define KCH      32
#define NCHUNK   (DIMC / KCH)        // 16
#define TILE_B2  8192                // 128 rows x 64B
#define STAGE_B  (2 * TILE_B2)       // A + B
#define NSTAGE   4
#define SMEM_GEMM (NSTAGE * STAGE_B) // 64 KB

template<int MODE>
__global__ __launch_bounds__(256)
void gemm_mma(const float* __restrict__ bias, float* __restrict__ C) {
    extern __shared__ char smem[];
    const int tid  = threadIdx.x;
    const int lane = tid & 31;
    const int wid  = tid >> 5;
    const int wm   = wid >> 2;
    const int wn   = wid & 3;
    const int m0 = blockIdx.y * 128;
    const int n0 = blockIdx.x * 128;

    const __half* A = (MODE == 1) ? g_x : g_o;
    const __half* B = (MODE == 1) ? g_w : g_p;

    const uint32_t sb = smem_u32(smem);
    const int frow = tid >> 1;
    const int fq0  = (tid & 1) * 2;

    float acc[4][4][4];
    #pragma unroll
    for (int i = 0; i < 4; i++)
        #pragma unroll
        for (int j = 0; j < 4; j++)
            #pragma unroll
            for (int k = 0; k < 4; k++) acc[i][j][k] = 0.f;

    // prologue: stages 0..2
    #pragma unroll
    for (int s = 0; s < NSTAGE - 1; s++) {
        const int k0 = s * KCH;
        const uint32_t base = sb + s * STAGE_B;
        cpa16(base + sw_off(frow, fq0),
              A + (size_t)(m0 + frow)*DIMC + k0 + fq0*8);
        cpa16(base + sw_off(frow, fq0 + 1),
              A + (size_t)(m0 + frow)*DIMC + k0 + fq0*8 + 8);
        cpa16(base + TILE_B2 + sw_off(frow, fq0),
              B + (size_t)(n0 + frow)*DIMC + k0 + fq0*8);
        cpa16(base + TILE_B2 + sw_off(frow, fq0 + 1),
              B + (size_t)(n0 + frow)*DIMC + k0 + fq0*8 + 8);
        asm volatile("cp.async.commit_group;" ::: "memory");
    }

    const int lr  = lane & 15;
    const int lq2 = lane >> 4;

    for (int c = 0; c < NCHUNK; c++) {
        asm volatile("cp.async.wait_group 2;" ::: "memory");
        __syncthreads();

        const uint32_t tba = sb + (uint32_t)(c & 3) * STAGE_B;
        #pragma unroll
        for (int ks = 0; ks < 2; ks++) {
            uint32_t af[4][4], bf[4][2];
            #pragma unroll
            for (int mt = 0; mt < 4; mt++) {
                uint32_t off = sw_off(wm*64 + mt*16 + lr, 2*ks + lq2);
                ldsm_x4(af[mt][0], af[mt][1], af[mt][2], af[mt][3], tba + off);
            }
            #pragma unroll
            for (int g2 = 0; g2 < 2; g2++) {
                uint32_t off = sw_off(wn*32 + g2*16 + lr, 2*ks + lq2);
                uint32_t t0, t1, t2, t3;
                ldsm_x4(t0, t1, t2, t3, tba + TILE_B2 + off);
                bf[2*g2][0] = t0; bf[2*g2][1] = t2;
                bf[2*g2+1][0] = t1; bf[2*g2+1][1] = t3;
            }
            #pragma unroll
            for (int mt = 0; mt < 4; mt++)
                #pragma unroll
                for (int nt = 0; nt < 4; nt++)
                    mma_f16(acc[mt][nt], af[mt], bf[nt]);
        }

        if (c + NSTAGE - 1 < NCHUNK) {
            const int s  = (c + NSTAGE - 1) & 3;
            const int k0 = (c + NSTAGE - 1) * KCH;
            const uint32_t base = sb + s * STAGE_B;
            cpa16(base + sw_off(frow, fq0),
                  A + (size_t)(m0 + frow)*DIMC + k0 + fq0*8);
            cpa16(base + sw_off(frow, fq0 + 1),
                  A + (size_t)(m0 + frow)*DIMC + k0 + fq0*8 + 8);
            cpa16(base + TILE_B2 + sw_off(frow, fq0),
                  B + (size_t)(n0 + frow)*DIMC + k0 + fq0*8);
            cpa16(base + TILE_B2 + sw_off(frow, fq0 + 1),
                  B + (size_t)(n0 + frow)*DIMC + k0 + fq0*8 + 8);
        }
        asm volatile("cp.async.commit_group;" ::: "memory");
    }

    // ---- epilogue
    if (MODE == 0) {
        #pragma unroll
        for (int mt = 0; mt < 4; mt++)
            #pragma unroll
            for (int nt = 0; nt < 4; nt++) {
                const int col = n0 + wn*32 + nt*8 + (lane & 3)*2;
                const float b0 = bias[col], b1 = bias[col + 1];
                #pragma unroll
                for (int half = 0; half < 2; half++) {
                    const int row = m0 + wm*64 + mt*16 + (lane >> 2) + half*8;
                    *(float2*)(C + (size_t)row*DIMC + col) =
                        make_float2(acc[mt][nt][2*half] + b0,
                                    acc[mt][nt][2*half + 1] + b1);
                }
            }
    } else {
        #pragma unroll
        for (int mt = 0; mt < 4; mt++)
            #pragma unroll
            for (int half = 0; half < 2; half++) {
                const int row = m0 + wm*64 + mt*16 + (lane >> 2) + half*8;
                const int b = row / NT;
                const int n = row - b*NT;
                const size_t base = ((size_t)b*NH*NT + n)*HD;
                #pragma unroll
                for (int nt = 0; nt < 4; nt++) {
                    const int col = n0 + wn*32 + nt*8 + (lane & 3)*2;
                    float vx = acc[mt][nt][2*half + 0] + bias[col];
                    float vy = acc[mt][nt][2*half + 1] + bias[col + 1];
                    const int which = col >> 9;          // 0=q 1=k 2=v
                    const int head  = (col & 511) >> 5;
                    const int d     = col & 31;
                    const size_t o  = base + (size_t)head*(NT*HD) + d;
                    if (which == 2) {
                        *(__half2*)(g_v + o) =
                            __halves2half2(__float2half_rn(vx), __float2half_rn(vy));
                    } else {
                        __half *dh, *dl;
                        if (which == 0) { dh = g_qh; dl = g_ql; vx *= QK_SCALE; vy *= QK_SCALE; }
                        else            { dh = g_kh; dl = g_kl; }
                        __half h0 = __float2half_rn(vx);
                        __half h1 = __float2half_rn(vy);
                        __half l0 = __float2half_rn(vx - __half2float(h0));
                        __half l1 = __float2half_rn(vy - __half2float(h1));
                        *(__half2*)(dh + o) = __halves2half2(h0, h1);
                        *(__half2*)(dl + o) = __halves2half2(l0, l1);
                    }
                }
            }
    }
}

// ---------------- HMMA attention: one block per (b,h), register softmax --------
#define AP      112
#define PPITCH  136                 // P fp16 pitch (elems); 272B rows

#define AT_QH 0
#define AT_QL (AT_QH + AP*64)
#define AT_KH (AT_QL + AP*64)
#define AT_KL (AT_KH + AP*64)
#define AT_VH (AT_KL + AP*64)
#define AT_PH (AT_VH + AP*64)
#define AT_BYTES (AT_PH + AP*PPITCH*2)   // 66304

__global__ __launch_bounds__(256, 2)
void attn_mma_kernel(const float* __restrict__ mask) {
    extern __shared__ char sm[];
    const int tid  = threadIdx.x;
    const int lane = tid & 31;
    const int wid  = tid >> 5;
    const int bh = blockIdx.x;
    const int b  = bh >> 4;
    const int h  = bh & 15;
    const int w  = b & (NWIN - 1);
    const uint32_t sb = smem_u32(sm);

    // ---- fill q(hi/lo), k(hi/lo), v(single) tiles; zero pad rows 98..111
    {
        const __half* gsrc[5] = { g_qh, g_ql, g_kh, g_kl, g_v };
        const size_t gbase = (size_t)bh * (NT*HD);
        for (int c = tid; c < 5*AP*4; c += 256) {
            int mat = c / (AP*4);
            int rem = c % (AP*4);
            int row = rem >> 2, q = rem & 3;
            uint4 val = make_uint4(0, 0, 0, 0);
            if (row < NT)
                val = *(const uint4*)(gsrc[mat] + gbase + (size_t)row*HD + q*8);
            *(uint4*)(sm + mat*AP*64 + sw_off(row, q)) = val;
        }
    }
    __syncthreads();

    const int lr  = lane & 15;
    const int lq2 = lane >> 4;

    // ---- S = Q K^T in registers (warp wid owns rows 16*wid..16*wid+15)
    if (wid < 7) {
        uint32_t qh[2][4], ql[2][4];
        #pragma unroll
        for (int ks = 0; ks < 2; ks++) {
            uint32_t off = sw_off(wid*16 + lr, 2*ks + lq2);
            ldsm_x4(qh[ks][0], qh[ks][1], qh[ks][2], qh[ks][3], sb + AT_QH + off);
            ldsm_x4(ql[ks][0], ql[ks][1], ql[ks][2], ql[ks][3], sb + AT_QL + off);
        }
        float c[7][2][4];
        #pragma unroll
        for (int nt = 0; nt < 7; nt++)
            #pragma unroll
            for (int n8 = 0; n8 < 2; n8++)
                #pragma unroll
                for (int e = 0; e < 4; e++) c[nt][n8][e] = 0.f;

        #pragma unroll
        for (int nt = 0; nt < 7; nt++) {
            #pragma unroll
            for (int ks = 0; ks < 2; ks++) {
                uint32_t t0, t1, t2, t3, u0, u1, u2, u3;
                uint32_t off = sw_off(nt*16 + lr, 2*ks + lq2);
                ldsm_x4(t0, t1, t2, t3, sb + AT_KH + off);
                ldsm_x4(u0, u1, u2, u3, sb + AT_KL + off);
                uint32_t kh0[2] = {t0, t2}, kh1[2] = {t1, t3};
                uint32_t kl0[2] = {u0, u2}, kl1[2] = {u1, u3};
                mma_f16(c[nt][0], qh[ks], kh0);
                mma_f16(c[nt][0], qh[ks], kl0);
                mma_f16(c[nt][0], ql[ks], kh0);
                mma_f16(c[nt][1], qh[ks], kh1);
                mma_f16(c[nt][1], qh[ks], kl1);
                mma_f16(c[nt][1], ql[ks], kh1);
            }
        }

        // ---- fused bias+mask, register softmax
        const int i0 = wid*16 + (lane >> 2);
        const int i1 = i0 + 8;
        const float* bi = g_bias + (size_t)h * (NT*NT);
        const float* mk = mask   + (size_t)w * (NT*NT);
        #pragma unroll
        for (int nt = 0; nt < 7; nt++)
            #pragma unroll
            for (int n8 = 0; n8 < 2; n8++) {
                int col = nt*16 + n8*8 + (lane & 3)*2;
                if (col < NT && i0 < NT) {
                    float2 bv = *(const float2*)(bi + (size_t)i0*NT + col);
                    float2 mv = *(const float2*)(mk + (size_t)i0*NT + col);
                    c[nt][n8][0] += bv.x + mv.x;
                    c[nt][n8][1] += bv.y + mv.y;
                } else { c[nt][n8][0] = -1e30f; c[nt][n8][1] = -1e30f; }
                if (col < NT && i1 < NT) {
                    float2 bv = *(const float2*)(bi + (size_t)i1*NT + col);
                    float2 mv = *(const float2*)(mk + (size_t)i1*NT + col);
                    c[nt][n8][2] += bv.x + mv.x;
                    c[nt][n8][3] += bv.y + mv.y;
                } else { c[nt][n8][2] = -1e30f; c[nt][n8][3] = -1e30f; }
            }

        float mx0 = -1e30f, mx1 = -1e30f;
        #pragma unroll
        for (int nt = 0; nt < 7; nt++)
            #pragma unroll
            for (int n8 = 0; n8 < 2; n8++) {
                mx0 = fmaxf(mx0, fmaxf(c[nt][n8][0], c[nt][n8][1]));
                mx1 = fmaxf(mx1, fmaxf(c[nt][n8][2], c[nt][n8][3]));
            }
        #pragma unroll
        for (int off = 1; off <= 2; off <<= 1) {
            mx0 = fmaxf(mx0, __shfl_xor_sync(0xffffffffu, mx0, off));
            mx1 = fmaxf(mx1, __shfl_xor_sync(0xffffffffu, mx1, off));
        }
        float s0 = 0.f, s1 = 0.f;
        #pragma unroll
        for (int nt = 0; nt < 7; nt++)
            #pragma unroll
            for (int n8 = 0; n8 < 2; n8++) {
                float e0 = __expf(c[nt][n8][0] - mx0);
                float e1 = __expf(c[nt][n8][1] - mx0);
                float e2 = __expf(c[nt][n8][2] - mx1);
                float e3 = __expf(c[nt][n8][3] - mx1);
                c[nt][n8][0] = e0; c[nt][n8][1] = e1;
                c[nt][n8][2] = e2; c[nt][n8][3] = e3;
                s0 += e0 + e1; s1 += e2 + e3;
            }
        #pragma unroll
        for (int off = 1; off <= 2; off <<= 1) {
            s0 += __shfl_xor_sync(0xffffffffu, s0, off);
            s1 += __shfl_xor_sync(0xffffffffu, s1, off);
        }
        const float r0 = 1.f / s0, r1 = 1.f / s1;

        __half* Ph = (__half*)(sm + AT_PH);
        #pragma unroll
        for (int nt = 0; nt < 7; nt++)
            #pragma unroll
            for (int n8 = 0; n8 < 2; n8++) {
                int col = nt*16 + n8*8 + (lane & 3)*2;
                *(__half2*)(Ph + (size_t)i0*PPITCH + col) =
                    __halves2half2(__float2half_rn(c[nt][n8][0] * r0),
                                   __float2half_rn(c[nt][n8][1] * r0));
                *(__half2*)(Ph + (size_t)i1*PPITCH + col) =
                    __halves2half2(__float2half_rn(c[nt][n8][2] * r1),
                                   __float2half_rn(c[nt][n8][3] * r1));
            }
    }
    __syncthreads();

    // ---- out = P V (single fp16 x single fp16), store g_o
    for (int pos = wid; pos < 14; pos += 8) {
        int mt = pos >> 1, nt = pos & 1;
        float cc[2][4] = {};
        for (int kt = 0; kt < 7; kt++) {
            uint32_t pa[4];
            uint32_t offp = (uint32_t)(mt*16 + lr)*(PPITCH*2) + (uint32_t)(kt*2 + lq2)*16;
            ldsm_x4(pa[0], pa[1], pa[2], pa[3], sb + AT_PH + offp);
            uint32_t offv = sw_off(kt*16 + lr, nt*2 + lq2);
            uint32_t t0, t1, t2, t3;
            ldsm_x4_t(t0, t1, t2, t3, sb + AT_VH + offv);
            uint32_t vh0[2] = {t0, t1}, vh1[2] = {t2, t3};
            mma_f16(cc[0], pa, vh0);
            mma_f16(cc[1], pa, vh1);
        }
        #pragma unroll
        for (int n8 = 0; n8 < 2; n8++)
            #pragma unroll
            for (int half = 0; half < 2; half++) {
                int i = mt*16 + (lane >> 2) + half*8;
                if (i < NT) {
                    int d = nt*16 + n8*8 + (lane & 3)*2;
                    size_t o = (size_t)(b*NT + i)*DIMC + h*HD + d;
                    *(__half2*)(g_o + o) =
                        __halves2half2(__float2half_rn(cc[n8][2*half]),
                                       __float2half_rn(cc[n8][2*half + 1]));
                }
            }
    }
}

// ---------------- launch --------------------------------------------------------
extern "C" void kernel_launch(void* const* d_in, const int* in_sizes, int n_in,
                              void* d_out, int out_size) {
    const float* x          = (const float*)d_in[0];
    const float* mask       = (const float*)d_in[1];
    const float* qkv_w      = (const float*)d_in[2];
    const float* qkv_b      = (const float*)d_in[3];
    const float* proj_w     = (const float*)d_in[4];
    const float* proj_b     = (const float*)d_in[5];
    const float* bias_table = (const float*)d_in[6];
    const int*   rel_index  = (const int*)  d_in[7];
    float* out = (float*)d_out;

    cudaFuncSetAttribute(attn_mma_kernel,
                         cudaFuncAttributeMaxDynamicSharedMemorySize, AT_BYTES);
    cudaFuncSetAttribute(gemm_mma<0>,
                         cudaFuncAttributeMaxDynamicSharedMemorySize, SMEM_GEMM);
    cudaFuncSetAttribute(gemm_mma<1>,
                         cudaFuncAttributeMaxDynamicSharedMemorySize, SMEM_GEMM);

    pre_kernel<<<PRE_BLOCKS, 256>>>(x, qkv_w, proj_w, bias_table, rel_index);
    gemm_mma<1><<<dim3(3*DIMC/128, MROWS/128), 256, SMEM_GEMM>>>(qkv_b, nullptr);
    attn_mma_kernel<<<NB*NH, 256, AT_BYTES>>>(mask);
    gemm_mma<0><<<dim3(DIMC/128, MROWS/128), 256, SMEM_GEMM>>>(proj_b, out);
}

// round 12
// speedup vs baseline: 5.3842x; 1.2095x over previous
#include <cuda_runtime.h>
#include <cuda_fp16.h>
#include <math.h>
#include <stdint.h>

#define NB    512
#define NT    98
#define DIMC  512
#define NH    16
#define HD    32
#define NWIN  64
#define MROWS (NB*NT)                 // 50176
#define QK_SCALE 0.17677669529663687f

// ---------------- scratch (device globals; no runtime alloc) ---------------
__device__ __align__(16) __half g_x [(size_t)MROWS*DIMC];    // x fp16
__device__ __align__(16) __half g_w [(size_t)3*DIMC*DIMC];   // qkv_w fp16
__device__ __align__(16) __half g_p [(size_t)DIMC*DIMC];     // proj_w fp16
__device__ __align__(16) __half g_o [(size_t)MROWS*DIMC];    // attn out fp16

// q single, k hi/lo, v single fp16; layout [(b*NH+h)*NT + n][HD]
__device__ __align__(16) __half g_q [(size_t)NB*NH*NT*HD];
__device__ __align__(16) __half g_kh[(size_t)NB*NH*NT*HD];
__device__ __align__(16) __half g_kl[(size_t)NB*NH*NT*HD];
__device__ __align__(16) __half g_v [(size_t)NB*NH*NT*HD];

__device__ float g_bias[NH*NT*NT];

// ---------------- helpers ----------------------------------------------------
__device__ __forceinline__ uint32_t smem_u32(const void* p) {
    uint32_t a;
    asm("{ .reg .u64 t; cvta.to.shared.u64 t, %1; cvt.u32.u64 %0, t; }"
        : "=r"(a) : "l"(p));
    return a;
}
__device__ __forceinline__ void ldsm_x4(uint32_t& r0, uint32_t& r1,
                                        uint32_t& r2, uint32_t& r3, uint32_t addr) {
    asm volatile("ldmatrix.sync.aligned.m8n8.x4.shared.b16 {%0,%1,%2,%3}, [%4];"
                 : "=r"(r0), "=r"(r1), "=r"(r2), "=r"(r3) : "r"(addr));
}
__device__ __forceinline__ void ldsm_x4_t(uint32_t& r0, uint32_t& r1,
                                          uint32_t& r2, uint32_t& r3, uint32_t addr) {
    asm volatile("ldmatrix.sync.aligned.m8n8.x4.trans.shared.b16 {%0,%1,%2,%3}, [%4];"
                 : "=r"(r0), "=r"(r1), "=r"(r2), "=r"(r3) : "r"(addr));
}
__device__ __forceinline__ void mma_f16(float* c, const uint32_t* a, const uint32_t* b) {
    asm volatile(
        "mma.sync.aligned.m16n8k16.row.col.f32.f16.f16.f32 "
        "{%0,%1,%2,%3}, {%4,%5,%6,%7}, {%8,%9}, {%0,%1,%2,%3};"
        : "+f"(c[0]), "+f"(c[1]), "+f"(c[2]), "+f"(c[3])
        : "r"(a[0]), "r"(a[1]), "r"(a[2]), "r"(a[3]), "r"(b[0]), "r"(b[1]));
}
__device__ __forceinline__ void cpa16(uint32_t saddr, const void* g) {
    asm volatile("cp.async.cg.shared.global [%0], [%1], 16;"
                 :: "r"(saddr), "l"(g) : "memory");
}
__device__ __forceinline__ uint32_t packh2(float a, float b) {
    __half2 h = __halves2half2(__float2half_rn(a), __float2half_rn(b));
    return *(uint32_t*)&h;
}
// byte offset in a [rows]x32-fp16 tile (64B rows) for (row, 16B-quarter q)
__device__ __forceinline__ uint32_t sw_off(int row, int q) {
    return (uint32_t)(row * 64 + ((q ^ ((row >> 1) & 3)) << 4));
}

// ---------------- fused preprocessing: converts + bias gather -----------------
#define N8X  (MROWS*DIMC/8)
#define N8W  (3*DIMC*DIMC/8)
#define N8P  (DIMC*DIMC/8)
#define BX   (N8X/256)
#define BW   (N8W/256)
#define BP   (N8P/256)
#define BBIAS ((NH*NT*NT + 255)/256)
#define PRE_BLOCKS (BX + BW + BP + BBIAS)

__global__ void pre_kernel(const float* __restrict__ x,
                           const float* __restrict__ qkv_w,
                           const float* __restrict__ proj_w,
                           const float* __restrict__ bt,
                           const int*   __restrict__ ri) {
    int blk = blockIdx.x;
    if (blk < BX + BW + BP) {
        const float* src;
        __half2* dst;
        int i;
        if (blk < BX)            { src = x;      dst = (__half2*)g_x; i = blk*256 + threadIdx.x; }
        else if (blk < BX + BW)  { src = qkv_w;  dst = (__half2*)g_w; i = (blk-BX)*256 + threadIdx.x; }
        else                     { src = proj_w; dst = (__half2*)g_p; i = (blk-BX-BW)*256 + threadIdx.x; }
        float4 a = ((const float4*)src)[2*i];
        float4 b = ((const float4*)src)[2*i + 1];
        dst[4*i + 0] = __halves2half2(__float2half_rn(a.x), __float2half_rn(a.y));
        dst[4*i + 1] = __halves2half2(__float2half_rn(a.z), __float2half_rn(a.w));
        dst[4*i + 2] = __halves2half2(__float2half_rn(b.x), __float2half_rn(b.y));
        dst[4*i + 3] = __halves2half2(__float2half_rn(b.z), __float2half_rn(b.w));
    } else {
        int idx = (blk - BX - BW - BP)*256 + threadIdx.x;
        if (idx < NH*NT*NT) {
            int h  = idx / (NT*NT);
            int ij = idx - h*(NT*NT);
            g_bias[idx] = bt[ri[ij]*NH + h];
        }
    }
}

// ---------------- HMMA fp16 GEMM (cp.async 4-stage pipeline) -------------------
#define KCH      32
#define NCHUNK   (DIMC / KCH)
#define TILE_B2  8192
#define STAGE_B  (2 * TILE_B2)
#define NSTAGE   4
#define SMEM_GEMM (NSTAGE * STAGE_B)

template<int MODE>
__global__ __launch_bounds__(256)
void gemm_mma(const float* __restrict__ bias, float* __restrict__ C) {
    extern __shared__ char smem[];
    const int tid  = threadIdx.x;
    const int lane = tid & 31;
    const int wid  = tid >> 5;
    const int wm   = wid >> 2;
    const int wn   = wid & 3;
    const int m0 = blockIdx.y * 128;
    const int n0 = blockIdx.x * 128;

    const __half* A = (MODE == 1) ? g_x : g_o;
    const __half* B = (MODE == 1) ? g_w : g_p;

    const uint32_t sb = smem_u32(smem);
    const int frow = tid >> 1;
    const int fq0  = (tid & 1) * 2;

    float acc[4][4][4];
    #pragma unroll
    for (int i = 0; i < 4; i++)
        #pragma unroll
        for (int j = 0; j < 4; j++)
            #pragma unroll
            for (int k = 0; k < 4; k++) acc[i][j][k] = 0.f;

    #pragma unroll
    for (int s = 0; s < NSTAGE - 1; s++) {
        const int k0 = s * KCH;
        const uint32_t base = sb + s * STAGE_B;
        cpa16(base + sw_off(frow, fq0),
              A + (size_t)(m0 + frow)*DIMC + k0 + fq0*8);
        cpa16(base + sw_off(frow, fq0 + 1),
              A + (size_t)(m0 + frow)*DIMC + k0 + fq0*8 + 8);
        cpa16(base + TILE_B2 + sw_off(frow, fq0),
              B + (size_t)(n0 + frow)*DIMC + k0 + fq0*8);
        cpa16(base + TILE_B2 + sw_off(frow, fq0 + 1),
              B + (size_t)(n0 + frow)*DIMC + k0 + fq0*8 + 8);
        asm volatile("cp.async.commit_group;" ::: "memory");
    }

    const int lr  = lane & 15;
    const int lq2 = lane >> 4;

    for (int c = 0; c < NCHUNK; c++) {
        asm volatile("cp.async.wait_group 2;" ::: "memory");
        __syncthreads();

        const uint32_t tba = sb + (uint32_t)(c & 3) * STAGE_B;
        #pragma unroll
        for (int ks = 0; ks < 2; ks++) {
            uint32_t af[4][4], bf[4][2];
            #pragma unroll
            for (int mt = 0; mt < 4; mt++) {
                uint32_t off = sw_off(wm*64 + mt*16 + lr, 2*ks + lq2);
                ldsm_x4(af[mt][0], af[mt][1], af[mt][2], af[mt][3], tba + off);
            }
            #pragma unroll
            for (int g2 = 0; g2 < 2; g2++) {
                uint32_t off = sw_off(wn*32 + g2*16 + lr, 2*ks + lq2);
                uint32_t t0, t1, t2, t3;
                ldsm_x4(t0, t1, t2, t3, tba + TILE_B2 + off);
                bf[2*g2][0] = t0; bf[2*g2][1] = t2;
                bf[2*g2+1][0] = t1; bf[2*g2+1][1] = t3;
            }
            #pragma unroll
            for (int mt = 0; mt < 4; mt++)
                #pragma unroll
                for (int nt = 0; nt < 4; nt++)
                    mma_f16(acc[mt][nt], af[mt], bf[nt]);
        }

        if (c + NSTAGE - 1 < NCHUNK) {
            const int s  = (c + NSTAGE - 1) & 3;
            const int k0 = (c + NSTAGE - 1) * KCH;
            const uint32_t base = sb + s * STAGE_B;
            cpa16(base + sw_off(frow, fq0),
                  A + (size_t)(m0 + frow)*DIMC + k0 + fq0*8);
            cpa16(base + sw_off(frow, fq0 + 1),
                  A + (size_t)(m0 + frow)*DIMC + k0 + fq0*8 + 8);
            cpa16(base + TILE_B2 + sw_off(frow, fq0),
                  B + (size_t)(n0 + frow)*DIMC + k0 + fq0*8);
            cpa16(base + TILE_B2 + sw_off(frow, fq0 + 1),
                  B + (size_t)(n0 + frow)*DIMC + k0 + fq0*8 + 8);
        }
        asm volatile("cp.async.commit_group;" ::: "memory");
    }

    // ---- epilogue
    if (MODE == 0) {
        #pragma unroll
        for (int mt = 0; mt < 4; mt++)
            #pragma unroll
            for (int nt = 0; nt < 4; nt++) {
                const int col = n0 + wn*32 + nt*8 + (lane & 3)*2;
                const float b0 = bias[col], b1 = bias[col + 1];
                #pragma unroll
                for (int half = 0; half < 2; half++) {
                    const int row = m0 + wm*64 + mt*16 + (lane >> 2) + half*8;
                    *(float2*)(C + (size_t)row*DIMC + col) =
                        make_float2(acc[mt][nt][2*half] + b0,
                                    acc[mt][nt][2*half + 1] + b1);
                }
            }
    } else {
        #pragma unroll
        for (int mt = 0; mt < 4; mt++)
            #pragma unroll
            for (int half = 0; half < 2; half++) {
                const int row = m0 + wm*64 + mt*16 + (lane >> 2) + half*8;
                const int b = row / NT;
                const int n = row - b*NT;
                const size_t base = ((size_t)b*NH*NT + n)*HD;
                #pragma unroll
                for (int nt = 0; nt < 4; nt++) {
                    const int col = n0 + wn*32 + nt*8 + (lane & 3)*2;
                    float vx = acc[mt][nt][2*half + 0] + bias[col];
                    float vy = acc[mt][nt][2*half + 1] + bias[col + 1];
                    const int which = col >> 9;          // 0=q 1=k 2=v
                    const int head  = (col & 511) >> 5;
                    const int d     = col & 31;
                    const size_t o  = base + (size_t)head*(NT*HD) + d;
                    if (which == 0) {
                        *(__half2*)(g_q + o) =
                            __halves2half2(__float2half_rn(vx * QK_SCALE),
                                           __float2half_rn(vy * QK_SCALE));
                    } else if (which == 2) {
                        *(__half2*)(g_v + o) =
                            __halves2half2(__float2half_rn(vx), __float2half_rn(vy));
                    } else {
                        __half h0 = __float2half_rn(vx);
                        __half h1 = __float2half_rn(vy);
                        __half l0 = __float2half_rn(vx - __half2float(h0));
                        __half l1 = __float2half_rn(vy - __half2float(h1));
                        *(__half2*)(g_kh + o) = __halves2half2(h0, h1);
                        *(__half2*)(g_kl + o) = __halves2half2(l0, l1);
                    }
                }
            }
    }
}

// ---------------- HMMA attention: register-resident P --------------------------
// 224 threads = 7 warps; warp wid owns output rows wid*16..wid*16+15.
#define AP      112
#define AT_Q  0
#define AT_KH (AP*64)
#define AT_KL (2*AP*64)
#define AT_V  (3*AP*64)
#define AT_BYTES (4*AP*64)      // 28672

__global__ __launch_bounds__(224)
void attn_mma_kernel(const float* __restrict__ mask) {
    extern __shared__ char sm[];
    const int tid  = threadIdx.x;
    const int lane = tid & 31;
    const int wid  = tid >> 5;
    const int bh = blockIdx.x;
    const int b  = bh >> 4;
    const int h  = bh & 15;
    const int w  = b & (NWIN - 1);
    const uint32_t sb = smem_u32(sm);

    // ---- fill q, k(hi/lo), v tiles; zero pad rows 98..111
    {
        const __half* gsrc[4] = { g_q, g_kh, g_kl, g_v };
        const size_t gbase = (size_t)bh * (NT*HD);
        for (int c = tid; c < 4*AP*4; c += 224) {
            int mat = c / (AP*4);
            int rem = c % (AP*4);
            int row = rem >> 2, q = rem & 3;
            uint4 val = make_uint4(0, 0, 0, 0);
            if (row < NT)
                val = *(const uint4*)(gsrc[mat] + gbase + (size_t)row*HD + q*8);
            *(uint4*)(sm + mat*AP*64 + sw_off(row, q)) = val;
        }
    }
    __syncthreads();

    const int lr  = lane & 15;
    const int lq2 = lane >> 4;

    // ---- S = Q K^T (q single, k hi/lo)
    uint32_t qf[2][4];
    #pragma unroll
    for (int ks = 0; ks < 2; ks++) {
        uint32_t off = sw_off(wid*16 + lr, 2*ks + lq2);
        ldsm_x4(qf[ks][0], qf[ks][1], qf[ks][2], qf[ks][3], sb + AT_Q + off);
    }
    float c[7][2][4];
    #pragma unroll
    for (int nt = 0; nt < 7; nt++)
        #pragma unroll
        for (int n8 = 0; n8 < 2; n8++)
            #pragma unroll
            for (int e = 0; e < 4; e++) c[nt][n8][e] = 0.f;

    #pragma unroll
    for (int nt = 0; nt < 7; nt++) {
        #pragma unroll
        for (int ks = 0; ks < 2; ks++) {
            uint32_t t0, t1, t2, t3, u0, u1, u2, u3;
            uint32_t off = sw_off(nt*16 + lr, 2*ks + lq2);
            ldsm_x4(t0, t1, t2, t3, sb + AT_KH + off);
            ldsm_x4(u0, u1, u2, u3, sb + AT_KL + off);
            uint32_t kh0[2] = {t0, t2}, kh1[2] = {t1, t3};
            uint32_t kl0[2] = {u0, u2}, kl1[2] = {u1, u3};
            mma_f16(c[nt][0], qf[ks], kh0);
            mma_f16(c[nt][0], qf[ks], kl0);
            mma_f16(c[nt][1], qf[ks], kh1);
            mma_f16(c[nt][1], qf[ks], kl1);
        }
    }

    // ---- fused bias+mask, register softmax
    const int i0 = wid*16 + (lane >> 2);
    const int i1 = i0 + 8;
    const float* bi = g_bias + (size_t)h * (NT*NT);
    const float* mk = mask   + (size_t)w * (NT*NT);
    #pragma unroll
    for (int nt = 0; nt < 7; nt++)
        #pragma unroll
        for (int n8 = 0; n8 < 2; n8++) {
            int col = nt*16 + n8*8 + (lane & 3)*2;
            if (col < NT && i0 < NT) {
                float2 bv = *(const float2*)(bi + (size_t)i0*NT + col);
                float2 mv = *(const float2*)(mk + (size_t)i0*NT + col);
                c[nt][n8][0] += bv.x + mv.x;
                c[nt][n8][1] += bv.y + mv.y;
            } else { c[nt][n8][0] = -1e30f; c[nt][n8][1] = -1e30f; }
            if (col < NT && i1 < NT) {
                float2 bv = *(const float2*)(bi + (size_t)i1*NT + col);
                float2 mv = *(const float2*)(mk + (size_t)i1*NT + col);
                c[nt][n8][2] += bv.x + mv.x;
                c[nt][n8][3] += bv.y + mv.y;
            } else { c[nt][n8][2] = -1e30f; c[nt][n8][3] = -1e30f; }
        }

    float mx0 = -1e30f, mx1 = -1e30f;
    #pragma unroll
    for (int nt = 0; nt < 7; nt++)
        #pragma unroll
        for (int n8 = 0; n8 < 2; n8++) {
            mx0 = fmaxf(mx0, fmaxf(c[nt][n8][0], c[nt][n8][1]));
            mx1 = fmaxf(mx1, fmaxf(c[nt][n8][2], c[nt][n8][3]));
        }
    #pragma unroll
    for (int off = 1; off <= 2; off <<= 1) {
        mx0 = fmaxf(mx0, __shfl_xor_sync(0xffffffffu, mx0, off));
        mx1 = fmaxf(mx1, __shfl_xor_sync(0xffffffffu, mx1, off));
    }
    float s0 = 0.f, s1 = 0.f;
    #pragma unroll
    for (int nt = 0; nt < 7; nt++)
        #pragma unroll
        for (int n8 = 0; n8 < 2; n8++) {
            float e0 = __expf(c[nt][n8][0] - mx0);
            float e1 = __expf(c[nt][n8][1] - mx0);
            float e2 = __expf(c[nt][n8][2] - mx1);
            float e3 = __expf(c[nt][n8][3] - mx1);
            c[nt][n8][0] = e0; c[nt][n8][1] = e1;
            c[nt][n8][2] = e2; c[nt][n8][3] = e3;
            s0 += e0 + e1; s1 += e2 + e3;
        }
    #pragma unroll
    for (int off = 1; off <= 2; off <<= 1) {
        s0 += __shfl_xor_sync(0xffffffffu, s0, off);
        s1 += __shfl_xor_sync(0xffffffffu, s1, off);
    }
    const float r0 = 1.f / s0, r1 = 1.f / s1;

    // ---- convert P c-frags -> PV a-frags in registers (no smem round trip)
    uint32_t pa[7][4];
    #pragma unroll
    for (int nt = 0; nt < 7; nt++) {
        pa[nt][0] = packh2(c[nt][0][0] * r0, c[nt][0][1] * r0);
        pa[nt][1] = packh2(c[nt][0][2] * r1, c[nt][0][3] * r1);
        pa[nt][2] = packh2(c[nt][1][0] * r0, c[nt][1][1] * r0);
        pa[nt][3] = packh2(c[nt][1][2] * r1, c[nt][1][3] * r1);
    }

    // ---- out = P V (each warp: its 16 rows x all 32 cols)
    float oc[4][4];
    #pragma unroll
    for (int j = 0; j < 4; j++)
        #pragma unroll
        for (int e = 0; e < 4; e++) oc[j][e] = 0.f;

    #pragma unroll
    for (int kt = 0; kt < 7; kt++) {
        #pragma unroll
        for (int vt = 0; vt < 2; vt++) {
            uint32_t t0, t1, t2, t3;
            ldsm_x4_t(t0, t1, t2, t3, sb + AT_V + sw_off(kt*16 + lr, vt*2 + lq2));
            uint32_t b0[2] = {t0, t1}, b1[2] = {t2, t3};
            mma_f16(oc[vt*2 + 0], pa[kt], b0);
            mma_f16(oc[vt*2 + 1], pa[kt], b1);
        }
    }

    // ---- store (fp16, proj-input layout)
    #pragma unroll
    for (int j = 0; j < 4; j++) {
        const int d = j*8 + (lane & 3)*2;
        if (i0 < NT)
            *(__half2*)(g_o + (size_t)(b*NT + i0)*DIMC + h*HD + d) =
                __halves2half2(__float2half_rn(oc[j][0]), __float2half_rn(oc[j][1]));
        if (i1 < NT)
            *(__half2*)(g_o + (size_t)(b*NT + i1)*DIMC + h*HD + d) =
                __halves2half2(__float2half_rn(oc[j][2]), __float2half_rn(oc[j][3]));
    }
}

// ---------------- launch --------------------------------------------------------
extern "C" void kernel_launch(void* const* d_in, const int* in_sizes, int n_in,
                              void* d_out, int out_size) {
    const float* x          = (const float*)d_in[0];
    const float* mask       = (const float*)d_in[1];
    const float* qkv_w      = (const float*)d_in[2];
    const float* qkv_b      = (const float*)d_in[3];
    const float* proj_w     = (const float*)d_in[4];
    const float* proj_b     = (const float*)d_in[5];
    const float* bias_table = (const float*)d_in[6];
    const int*   rel_index  = (const int*)  d_in[7];
    float* out = (float*)d_out;

    cudaFuncSetAttribute(attn_mma_kernel,
                         cudaFuncAttributeMaxDynamicSharedMemorySize, AT_BYTES);
    cudaFuncSetAttribute(gemm_mma<0>,
                         cudaFuncAttributeMaxDynamicSharedMemorySize, SMEM_GEMM);
    cudaFuncSetAttribute(gemm_mma<1>,
                         cudaFuncAttributeMaxDynamicSharedMemorySize, SMEM_GEMM);

    pre_kernel<<<PRE_BLOCKS, 256>>>(x, qkv_w, proj_w, bias_table, rel_index);
    gemm_mma<1><<<dim3(3*DIMC/128, MROWS/128), 256, SMEM_GEMM>>>(qkv_b, nullptr);
    attn_mma_kernel<<<NB*NH, 224, AT_BYTES>>>(mask);
    gemm_mma<0><<<dim3(DIMC/128, MROWS/128), 256, SMEM_GEMM>>>(proj_b, out);
}

// round 13
// speedup vs baseline: 6.3129x; 1.1725x over previous
#include <cuda_runtime.h>
#include <cuda_fp16.h>
#include <math.h>
#include <stdint.h>

#define NB    512
#define NT    98
#define DIMC  512
#define NH    16
#define HD    32
#define NWIN  64
#define MROWS (NB*NT)                 // 50176
#define QK_SCALE 0.17677669529663687f

// ---------------- scratch (device globals; no runtime alloc) ---------------
__device__ __align__(16) __half g_x [(size_t)MROWS*DIMC];    // x fp16
__device__ __align__(16) __half g_w [(size_t)3*DIMC*DIMC];   // qkv_w fp16
__device__ __align__(16) __half g_p [(size_t)DIMC*DIMC];     // proj_w fp16
__device__ __align__(16) __half g_o [(size_t)MROWS*DIMC];    // attn out fp16

// q single, k hi/lo, v single fp16; layout [(b*NH+h)*NT + n][HD]
__device__ __align__(16) __half g_q [(size_t)NB*NH*NT*HD];
__device__ __align__(16) __half g_kh[(size_t)NB*NH*NT*HD];
__device__ __align__(16) __half g_kl[(size_t)NB*NH*NT*HD];
__device__ __align__(16) __half g_v [(size_t)NB*NH*NT*HD];

__device__ float g_bias[NH*NT*NT];

// ---------------- helpers ----------------------------------------------------
__device__ __forceinline__ uint32_t smem_u32(const void* p) {
    uint32_t a;
    asm("{ .reg .u64 t; cvta.to.shared.u64 t, %1; cvt.u32.u64 %0, t; }"
        : "=r"(a) : "l"(p));
    return a;
}
__device__ __forceinline__ void ldsm_x4(uint32_t& r0, uint32_t& r1,
                                        uint32_t& r2, uint32_t& r3, uint32_t addr) {
    asm volatile("ldmatrix.sync.aligned.m8n8.x4.shared.b16 {%0,%1,%2,%3}, [%4];"
                 : "=r"(r0), "=r"(r1), "=r"(r2), "=r"(r3) : "r"(addr));
}
__device__ __forceinline__ void ldsm_x4_t(uint32_t& r0, uint32_t& r1,
                                          uint32_t& r2, uint32_t& r3, uint32_t addr) {
    asm volatile("ldmatrix.sync.aligned.m8n8.x4.trans.shared.b16 {%0,%1,%2,%3}, [%4];"
                 : "=r"(r0), "=r"(r1), "=r"(r2), "=r"(r3) : "r"(addr));
}
__device__ __forceinline__ void mma_f16(float* c, const uint32_t* a, const uint32_t* b) {
    asm volatile(
        "mma.sync.aligned.m16n8k16.row.col.f32.f16.f16.f32 "
        "{%0,%1,%2,%3}, {%4,%5,%6,%7}, {%8,%9}, {%0,%1,%2,%3};"
        : "+f"(c[0]), "+f"(c[1]), "+f"(c[2]), "+f"(c[3])
        : "r"(a[0]), "r"(a[1]), "r"(a[2]), "r"(a[3]), "r"(b[0]), "r"(b[1]));
}
__device__ __forceinline__ void cpa16(uint32_t saddr, const void* g) {
    asm volatile("cp.async.cg.shared.global [%0], [%1], 16;"
                 :: "r"(saddr), "l"(g) : "memory");
}
__device__ __forceinline__ uint32_t packh2(float a, float b) {
    __half2 h = __halves2half2(__float2half_rn(a), __float2half_rn(b));
    return *(uint32_t*)&h;
}
// 64B-row tile swizzle (attention tiles)
__device__ __forceinline__ uint32_t sw_off(int row, int q) {
    return (uint32_t)(row * 64 + ((q ^ ((row >> 1) & 3)) << 4));
}
// 128B-row tile swizzle (GEMM tiles): 8 16B-quarters XOR row&7
__device__ __forceinline__ uint32_t sw128o(int row, int q) {
    return (uint32_t)(row * 128 + ((q ^ (row & 7)) << 4));
}

// ---------------- fused preprocessing: converts + bias gather -----------------
#define N8X  (MROWS*DIMC/8)
#define N8W  (3*DIMC*DIMC/8)
#define N8P  (DIMC*DIMC/8)
#define BX   (N8X/256)
#define BW   (N8W/256)
#define BP   (N8P/256)
#define BBIAS ((NH*NT*NT + 255)/256)
#define PRE_BLOCKS (BX + BW + BP + BBIAS)

__global__ void pre_kernel(const float* __restrict__ x,
                           const float* __restrict__ qkv_w,
                           const float* __restrict__ proj_w,
                           const float* __restrict__ bt,
                           const int*   __restrict__ ri) {
    int blk = blockIdx.x;
    if (blk < BX + BW + BP) {
        const float* src;
        __half2* dst;
        int i;
        if (blk < BX)            { src = x;      dst = (__half2*)g_x; i = blk*256 + threadIdx.x; }
        else if (blk < BX + BW)  { src = qkv_w;  dst = (__half2*)g_w; i = (blk-BX)*256 + threadIdx.x; }
        else                     { src = proj_w; dst = (__half2*)g_p; i = (blk-BX-BW)*256 + threadIdx.x; }
        float4 a = ((const float4*)src)[2*i];
        float4 b = ((const float4*)src)[2*i + 1];
        dst[4*i + 0] = __halves2half2(__float2half_rn(a.x), __float2half_rn(a.y));
        dst[4*i + 1] = __halves2half2(__float2half_rn(a.z), __float2half_rn(a.w));
        dst[4*i + 2] = __halves2half2(__float2half_rn(b.x), __float2half_rn(b.y));
        dst[4*i + 3] = __halves2half2(__float2half_rn(b.z), __float2half_rn(b.w));
    } else {
        int idx = (blk - BX - BW - BP)*256 + threadIdx.x;
        if (idx < NH*NT*NT) {
            int h  = idx / (NT*NT);
            int ij = idx - h*(NT*NT);
            g_bias[idx] = bt[ri[ij]*NH + h];
        }
    }
}

// ---------------- HMMA fp16 GEMM (cp.async 3-stage, K-chunk 64) ----------------
// C[M,N] = A[M,512] @ B[N,512]^T + bias[N]
// MODE 1: A=g_x, B=g_w (N=1536), scatter q/k/v
// MODE 0: A=g_o, B=g_p (N=512), fp32 write to d_out
#define KCH      64
#define NCHUNK   (DIMC / KCH)        // 8
#define TILE_B2  16384               // 128 rows x 128B
#define STAGE_B  (2 * TILE_B2)       // A + B = 32 KB
#define NSTAGE   3
#define SMEM_GEMM (NSTAGE * STAGE_B) // 96 KB

template<int MODE>
__global__ __launch_bounds__(256, 2)
void gemm_mma(const float* __restrict__ bias, float* __restrict__ C) {
    extern __shared__ char smem[];
    const int tid  = threadIdx.x;
    const int lane = tid & 31;
    const int wid  = tid >> 5;
    const int wm   = wid >> 2;
    const int wn   = wid & 3;
    const int m0 = blockIdx.y * 128;
    const int n0 = blockIdx.x * 128;

    const __half* A = (MODE == 1) ? g_x : g_o;
    const __half* B = (MODE == 1) ? g_w : g_p;

    const uint32_t sb = smem_u32(smem);

    float acc[4][4][4];
    #pragma unroll
    for (int i = 0; i < 4; i++)
        #pragma unroll
        for (int j = 0; j < 4; j++)
            #pragma unroll
            for (int k = 0; k < 4; k++) acc[i][j][k] = 0.f;

    // stage fill: 1024 16B units per tile, 256 threads -> 4 units each (A and B)
    #define FILL_STAGE(SBASE, K0)                                               \
        {                                                                       \
            _Pragma("unroll")                                                   \
            for (int t = 0; t < 4; t++) {                                       \
                int u = tid + 256*t;                                            \
                int row = u >> 3, q = u & 7;                                    \
                cpa16((SBASE) + sw128o(row, q),                                 \
                      A + (size_t)(m0 + row)*DIMC + (K0) + q*8);                \
                cpa16((SBASE) + TILE_B2 + sw128o(row, q),                       \
                      B + (size_t)(n0 + row)*DIMC + (K0) + q*8);                \
            }                                                                   \
        }

    // prologue: stages 0,1
    FILL_STAGE(sb + 0*STAGE_B, 0);
    asm volatile("cp.async.commit_group;" ::: "memory");
    FILL_STAGE(sb + 1*STAGE_B, KCH);
    asm volatile("cp.async.commit_group;" ::: "memory");

    const int lr  = lane & 15;
    const int lq2 = lane >> 4;
    int stage = 0;

    for (int c = 0; c < NCHUNK; c++) {
        asm volatile("cp.async.wait_group 1;" ::: "memory");
        __syncthreads();

        // prefetch chunk c+2 into the stage consumed at chunk c-1
        if (c + 2 < NCHUNK) {
            int ps = stage + 2; if (ps >= NSTAGE) ps -= NSTAGE;
            FILL_STAGE(sb + ps*STAGE_B, (c + 2)*KCH);
        }
        asm volatile("cp.async.commit_group;" ::: "memory");

        const uint32_t tba = sb + (uint32_t)stage * STAGE_B;
        #pragma unroll
        for (int ks = 0; ks < 4; ks++) {
            const int qq = ks*2 + lq2;
            uint32_t af[4][4], bf[4][2];
            #pragma unroll
            for (int mt = 0; mt < 4; mt++) {
                uint32_t off = sw128o(wm*64 + mt*16 + lr, qq);
                ldsm_x4(af[mt][0], af[mt][1], af[mt][2], af[mt][3], tba + off);
            }
            #pragma unroll
            for (int g2 = 0; g2 < 2; g2++) {
                uint32_t off = sw128o(wn*32 + g2*16 + lr, qq);
                uint32_t t0, t1, t2, t3;
                ldsm_x4(t0, t1, t2, t3, tba + TILE_B2 + off);
                bf[2*g2][0] = t0; bf[2*g2][1] = t2;
                bf[2*g2+1][0] = t1; bf[2*g2+1][1] = t3;
            }
            #pragma unroll
            for (int mt = 0; mt < 4; mt++)
                #pragma unroll
                for (int nt = 0; nt < 4; nt++)
                    mma_f16(acc[mt][nt], af[mt], bf[nt]);
        }
        __syncthreads();
        stage++; if (stage >= NSTAGE) stage -= NSTAGE;
    }
    #undef FILL_STAGE

    // ---- epilogue
    if (MODE == 0) {
        #pragma unroll
        for (int mt = 0; mt < 4; mt++)
            #pragma unroll
            for (int nt = 0; nt < 4; nt++) {
                const int col = n0 + wn*32 + nt*8 + (lane & 3)*2;
                const float b0 = bias[col], b1 = bias[col + 1];
                #pragma unroll
                for (int half = 0; half < 2; half++) {
                    const int row = m0 + wm*64 + mt*16 + (lane >> 2) + half*8;
                    *(float2*)(C + (size_t)row*DIMC + col) =
                        make_float2(acc[mt][nt][2*half] + b0,
                                    acc[mt][nt][2*half + 1] + b1);
                }
            }
    } else {
        #pragma unroll
        for (int mt = 0; mt < 4; mt++)
            #pragma unroll
            for (int half = 0; half < 2; half++) {
                const int row = m0 + wm*64 + mt*16 + (lane >> 2) + half*8;
                const int b = row / NT;
                const int n = row - b*NT;
                const size_t base = ((size_t)b*NH*NT + n)*HD;
                #pragma unroll
                for (int nt = 0; nt < 4; nt++) {
                    const int col = n0 + wn*32 + nt*8 + (lane & 3)*2;
                    float vx = acc[mt][nt][2*half + 0] + bias[col];
                    float vy = acc[mt][nt][2*half + 1] + bias[col + 1];
                    const int which = col >> 9;          // 0=q 1=k 2=v
                    const int head  = (col & 511) >> 5;
                    const int d     = col & 31;
                    const size_t o  = base + (size_t)head*(NT*HD) + d;
                    if (which == 0) {
                        *(__half2*)(g_q + o) =
                            __halves2half2(__float2half_rn(vx * QK_SCALE),
                                           __float2half_rn(vy * QK_SCALE));
                    } else if (which == 2) {
                        *(__half2*)(g_v + o) =
                            __halves2half2(__float2half_rn(vx), __float2half_rn(vy));
                    } else {
                        __half h0 = __float2half_rn(vx);
                        __half h1 = __float2half_rn(vy);
                        __half l0 = __float2half_rn(vx - __half2float(h0));
                        __half l1 = __float2half_rn(vy - __half2float(h1));
                        *(__half2*)(g_kh + o) = __halves2half2(h0, h1);
                        *(__half2*)(g_kl + o) = __halves2half2(l0, l1);
                    }
                }
            }
    }
}

// ---------------- HMMA attention: register-resident P --------------------------
// 224 threads = 7 warps; warp wid owns output rows wid*16..wid*16+15.
#define AP      112
#define AT_Q  0
#define AT_KH (AP*64)
#define AT_KL (2*AP*64)
#define AT_V  (3*AP*64)
#define AT_BYTES (4*AP*64)      // 28672

__global__ __launch_bounds__(224)
void attn_mma_kernel(const float* __restrict__ mask) {
    extern __shared__ char sm[];
    const int tid  = threadIdx.x;
    const int lane = tid & 31;
    const int wid  = tid >> 5;
    const int bh = blockIdx.x;
    const int b  = bh >> 4;
    const int h  = bh & 15;
    const int w  = b & (NWIN - 1);
    const uint32_t sb = smem_u32(sm);

    // ---- fill q, k(hi/lo), v tiles; zero pad rows 98..111
    {
        const __half* gsrc[4] = { g_q, g_kh, g_kl, g_v };
        const size_t gbase = (size_t)bh * (NT*HD);
        for (int c = tid; c < 4*AP*4; c += 224) {
            int mat = c / (AP*4);
            int rem = c % (AP*4);
            int row = rem >> 2, q = rem & 3;
            uint4 val = make_uint4(0, 0, 0, 0);
            if (row < NT)
                val = *(const uint4*)(gsrc[mat] + gbase + (size_t)row*HD + q*8);
            *(uint4*)(sm + mat*AP*64 + sw_off(row, q)) = val;
        }
    }
    __syncthreads();

    const int lr  = lane & 15;
    const int lq2 = lane >> 4;

    // ---- S = Q K^T (q single, k hi/lo)
    uint32_t qf[2][4];
    #pragma unroll
    for (int ks = 0; ks < 2; ks++) {
        uint32_t off = sw_off(wid*16 + lr, 2*ks + lq2);
        ldsm_x4(qf[ks][0], qf[ks][1], qf[ks][2], qf[ks][3], sb + AT_Q + off);
    }
    float c[7][2][4];
    #pragma unroll
    for (int nt = 0; nt < 7; nt++)
        #pragma unroll
        for (int n8 = 0; n8 < 2; n8++)
            #pragma unroll
            for (int e = 0; e < 4; e++) c[nt][n8][e] = 0.f;

    #pragma unroll
    for (int nt = 0; nt < 7; nt++) {
        #pragma unroll
        for (int ks = 0; ks < 2; ks++) {
            uint32_t t0, t1, t2, t3, u0, u1, u2, u3;
            uint32_t off = sw_off(nt*16 + lr, 2*ks + lq2);
            ldsm_x4(t0, t1, t2, t3, sb + AT_KH + off);
            ldsm_x4(u0, u1, u2, u3, sb + AT_KL + off);
            uint32_t kh0[2] = {t0, t2}, kh1[2] = {t1, t3};
            uint32_t kl0[2] = {u0, u2}, kl1[2] = {u1, u3};
            mma_f16(c[nt][0], qf[ks], kh0);
            mma_f16(c[nt][0], qf[ks], kl0);
            mma_f16(c[nt][1], qf[ks], kh1);
            mma_f16(c[nt][1], qf[ks], kl1);
        }
    }

    // ---- fused bias+mask, register softmax
    const int i0 = wid*16 + (lane >> 2);
    const int i1 = i0 + 8;
    const float* bi = g_bias + (size_t)h * (NT*NT);
    const float* mk = mask   + (size_t)w * (NT*NT);
    #pragma unroll
    for (int nt = 0; nt < 7; nt++)
        #pragma unroll
        for (int n8 = 0; n8 < 2; n8++) {
            int col = nt*16 + n8*8 + (lane & 3)*2;
            if (col < NT && i0 < NT) {
                float2 bv = *(const float2*)(bi + (size_t)i0*NT + col);
                float2 mv = *(const float2*)(mk + (size_t)i0*NT + col);
                c[nt][n8][0] += bv.x + mv.x;
                c[nt][n8][1] += bv.y + mv.y;
            } else { c[nt][n8][0] = -1e30f; c[nt][n8][1] = -1e30f; }
            if (col < NT && i1 < NT) {
                float2 bv = *(const float2*)(bi + (size_t)i1*NT + col);
                float2 mv = *(const float2*)(mk + (size_t)i1*NT + col);
                c[nt][n8][2] += bv.x + mv.x;
                c[nt][n8][3] += bv.y + mv.y;
            } else { c[nt][n8][2] = -1e30f; c[nt][n8][3] = -1e30f; }
        }

    float mx0 = -1e30f, mx1 = -1e30f;
    #pragma unroll
    for (int nt = 0; nt < 7; nt++)
        #pragma unroll
        for (int n8 = 0; n8 < 2; n8++) {
            mx0 = fmaxf(mx0, fmaxf(c[nt][n8][0], c[nt][n8][1]));
            mx1 = fmaxf(mx1, fmaxf(c[nt][n8][2], c[nt][n8][3]));
        }
    #pragma unroll
    for (int off = 1; off <= 2; off <<= 1) {
        mx0 = fmaxf(mx0, __shfl_xor_sync(0xffffffffu, mx0, off));
        mx1 = fmaxf(mx1, __shfl_xor_sync(0xffffffffu, mx1, off));
    }
    float s0 = 0.f, s1 = 0.f;
    #pragma unroll
    for (int nt = 0; nt < 7; nt++)
        #pragma unroll
        for (int n8 = 0; n8 < 2; n8++) {
            float e0 = __expf(c[nt][n8][0] - mx0);
            float e1 = __expf(c[nt][n8][1] - mx0);
            float e2 = __expf(c[nt][n8][2] - mx1);
            float e3 = __expf(c[nt][n8][3] - mx1);
            c[nt][n8][0] = e0; c[nt][n8][1] = e1;
            c[nt][n8][2] = e2; c[nt][n8][3] = e3;
            s0 += e0 + e1; s1 += e2 + e3;
        }
    #pragma unroll
    for (int off = 1; off <= 2; off <<= 1) {
        s0 += __shfl_xor_sync(0xffffffffu, s0, off);
        s1 += __shfl_xor_sync(0xffffffffu, s1, off);
    }
    const float r0 = 1.f / s0, r1 = 1.f / s1;

    // ---- convert P c-frags -> PV a-frags in registers
    uint32_t pa[7][4];
    #pragma unroll
    for (int nt = 0; nt < 7; nt++) {
        pa[nt][0] = packh2(c[nt][0][0] * r0, c[nt][0][1] * r0);
        pa[nt][1] = packh2(c[nt][0][2] * r1, c[nt][0][3] * r1);
        pa[nt][2] = packh2(c[nt][1][0] * r0, c[nt][1][1] * r0);
        pa[nt][3] = packh2(c[nt][1][2] * r1, c[nt][1][3] * r1);
    }

    // ---- out = P V
    float oc[4][4];
    #pragma unroll
    for (int j = 0; j < 4; j++)
        #pragma unroll
        for (int e = 0; e < 4; e++) oc[j][e] = 0.f;

    #pragma unroll
    for (int kt = 0; kt < 7; kt++) {
        #pragma unroll
        for (int vt = 0; vt < 2; vt++) {
            uint32_t t0, t1, t2, t3;
            ldsm_x4_t(t0, t1, t2, t3, sb + AT_V + sw_off(kt*16 + lr, vt*2 + lq2));
            uint32_t b0[2] = {t0, t1}, b1[2] = {t2, t3};
            mma_f16(oc[vt*2 + 0], pa[kt], b0);
            mma_f16(oc[vt*2 + 1], pa[kt], b1);
        }
    }

    // ---- store (fp16, proj-input layout)
    #pragma unroll
    for (int j = 0; j < 4; j++) {
        const int d = j*8 + (lane & 3)*2;
        if (i0 < NT)
            *(__half2*)(g_o + (size_t)(b*NT + i0)*DIMC + h*HD + d) =
                __halves2half2(__float2half_rn(oc[j][0]), __float2half_rn(oc[j][1]));
        if (i1 < NT)
            *(__half2*)(g_o + (size_t)(b*NT + i1)*DIMC + h*HD + d) =
                __halves2half2(__float2half_rn(oc[j][2]), __float2half_rn(oc[j][3]));
    }
}

// ---------------- launch --------------------------------------------------------
extern "C" void kernel_launch(void* const* d_in, const int* in_sizes, int n_in,
                              void* d_out, int out_size) {
    const float* x          = (const float*)d_in[0];
    const float* mask       = (const float*)d_in[1];
    const float* qkv_w      = (const float*)d_in[2];
    const float* qkv_b      = (const float*)d_in[3];
    const float* proj_w     = (const float*)d_in[4];
    const float* proj_b     = (const float*)d_in[5];
    const float* bias_table = (const float*)d_in[6];
    const int*   rel_index  = (const int*)  d_in[7];
    float* out = (float*)d_out;

    cudaFuncSetAttribute(attn_mma_kernel,
                         cudaFuncAttributeMaxDynamicSharedMemorySize, AT_BYTES);
    cudaFuncSetAttribute(gemm_mma<0>,
                         cudaFuncAttributeMaxDynamicSharedMemorySize, SMEM_GEMM);
    cudaFuncSetAttribute(gemm_mma<1>,
                         cudaFuncAttributeMaxDynamicSharedMemorySize, SMEM_GEMM);

    pre_kernel<<<PRE_BLOCKS, 256>>>(x, qkv_w, proj_w, bias_table, rel_index);
    gemm_mma<1><<<dim3(3*DIMC/128, MROWS/128), 256, SMEM_GEMM>>>(qkv_b, nullptr);
    attn_mma_kernel<<<NB*NH, 224, AT_BYTES>>>(mask);
    gemm_mma<0><<<dim3(DIMC/128, MROWS/128), 256, SMEM_GEMM>>>(proj_b, out);
}